// round 12
// baseline (speedup 1.0000x reference)
#include <cuda_runtime.h>

#define BB 8
#define N_IN 20000
#define NPAD 20480
#define N_ALL 1200
#define NPT 1024
#define KNB 34
#define CC 96
#define HH 6
#define NROWS (BB*NPT)

// ---------------- scratch (device globals; no allocation allowed) ----------------
__device__ float d_xs[BB*NPAD];
__device__ float d_ys[BB*NPAD];
__device__ float d_zs[BB*NPAD];
__device__ int   d_fps[BB*N_ALL];
__device__ float d_coord[NROWS*3];
__device__ float d_color[NROWS*3];
__device__ int   d_nidx[NROWS*KNB];
__device__ int   d_ncnt[NROWS];
__device__ float d_x [NROWS*CC];
__device__ float d_qb[NROWS*CC];
__device__ float d_kb[NROWS*CC];
__device__ float d_vb[NROWS*CC];
__device__ float d_ao[NROWS*CC];
__device__ float d_x1[NROWS*CC];

// ---------------- 0: SoA transpose of point clouds (pad with point 0 clone) -------
__global__ void k_transpose(const float* __restrict__ pc) {
    int idx = blockIdx.x*blockDim.x + threadIdx.x;
    if (idx >= BB*NPAD) return;
    int b = idx / NPAD, i = idx - b*NPAD;
    int src = (i < N_IN) ? i : 0;                 // pad = clone of point 0 (dist->0, never argmax)
    const float* p = pc + ((long)b*N_IN + src)*3;
    d_xs[idx] = p[0]; d_ys[idx] = p[1]; d_zs[idx] = p[2];
}

// ---------------- 1: farthest point sampling, 1 block per batch -------------------
__global__ __launch_bounds__(512, 1) void k_fps() {
    const int b = blockIdx.x, tid = threadIdx.x;
    const int lane = tid & 31, wid = tid >> 5;
    const float4* X4 = (const float4*)(d_xs + b*NPAD);
    const float4* Y4 = (const float4*)(d_ys + b*NPAD);
    const float4* Z4 = (const float4*)(d_zs + b*NPAD);
    const float* Xs = d_xs + b*NPAD;
    const float* Ys = d_ys + b*NPAD;
    const float* Zs = d_zs + b*NPAD;

    float dist[40];
#pragma unroll
    for (int i = 0; i < 40; ++i) dist[i] = 1e10f;

    __shared__ float s_v[16];
    __shared__ int   s_i[16];
    __shared__ int   s_cur;

    int cur = 0;
    for (int t = 0; t < N_ALL; ++t) {
        if (tid == 0) d_fps[b*N_ALL + t] = cur;
        float cx = __ldg(Xs + cur), cy = __ldg(Ys + cur), cz = __ldg(Zs + cur);
        float best = -1.0f; int bidx = 0;
#pragma unroll
        for (int k = 0; k < 10; ++k) {
            int f4 = k*512 + tid;                 // block-strided: warp reads contiguous 512B
            float4 px = X4[f4], py = Y4[f4], pz = Z4[f4];
#pragma unroll
            for (int m = 0; m < 4; ++m) {
                float x = (m==0)?px.x:(m==1)?px.y:(m==2)?px.z:px.w;
                float y = (m==0)?py.x:(m==1)?py.y:(m==2)?py.z:py.w;
                float z = (m==0)?pz.x:(m==1)?pz.y:(m==2)?pz.z:pz.w;
                float dx = __fadd_rn(x, -cx);
                float dy = __fadd_rn(y, -cy);
                float dz = __fadd_rn(z, -cz);
                // match XLA: mul then summed adds, no fma contraction
                float d = __fadd_rn(__fadd_rn(__fmul_rn(dx,dx), __fmul_rn(dy,dy)), __fmul_rn(dz,dz));
                int idx = k*40; // placeholder, recomputed below
                (void)idx;
                float nd = fminf(dist[k*4+m], d);
                dist[k*4+m] = nd;
                int j = f4*4 + m;
                if (nd > best) { best = nd; bidx = j; }   // strict > : first occurrence wins
            }
        }
        // warp argmax reduce (tie -> lower index)
#pragma unroll
        for (int off = 16; off > 0; off >>= 1) {
            float ov = __shfl_down_sync(0xffffffffu, best, off);
            int   oi = __shfl_down_sync(0xffffffffu, bidx, off);
            if (ov > best || (ov == best && oi < bidx)) { best = ov; bidx = oi; }
        }
        if (lane == 0) { s_v[wid] = best; s_i[wid] = bidx; }
        __syncthreads();
        if (tid == 0) {
            float bv = s_v[0]; int bi = s_i[0];
#pragma unroll
            for (int w = 1; w < 16; ++w) {
                float ov = s_v[w]; int oi = s_i[w];
                if (ov > bv || (ov == bv && oi < bi)) { bv = ov; bi = oi; }
            }
            s_cur = bi;
        }
        __syncthreads();
        cur = s_cur;
    }
}

// ---------------- 2: gather selected points (fps_idx[:, sel]) --------------------
__global__ void k_gather(const float* __restrict__ pc, const float* __restrict__ col,
                         const int* __restrict__ sel, float* __restrict__ out_coord) {
    int p = blockIdx.x*blockDim.x + threadIdx.x;
    if (p >= NROWS) return;
    int b = p >> 10, i = p & 1023;
    int gi = d_fps[b*N_ALL + sel[i]];
    const float* s  = pc  + ((long)b*N_IN + gi)*3;
    const float* s2 = col + ((long)b*N_IN + gi)*3;
    d_coord[p*3+0] = s[0];  d_coord[p*3+1] = s[1];  d_coord[p*3+2] = s[2];
    d_color[p*3+0] = s2[0]; d_color[p*3+1] = s2[1]; d_color[p*3+2] = s2[2];
    out_coord[p*3+0] = s[0]; out_coord[p*3+1] = s[1]; out_coord[p*3+2] = s[2];
}

// ---------------- 3: radius neighbors, one warp per query point ------------------
__global__ __launch_bounds__(256) void k_neighbor() {
    __shared__ float sx[NPT], sy[NPT], sz[NPT];
    const int b = blockIdx.y;
    for (int i = threadIdx.x; i < NPT; i += 256) {
        const float* cp = d_coord + (b*NPT + i)*3;
        sx[i] = cp[0]; sy[i] = cp[1]; sz[i] = cp[2];
    }
    __syncthreads();
    const int warp = threadIdx.x >> 5, lane = threadIdx.x & 31;
    const int pl = blockIdx.x*8 + warp;
    const int p  = b*NPT + pl;
    const float qx = sx[pl], qy = sy[pl], qz = sz[pl];
    const float R2 = 0.010000000000000002f;
    float key[32];
    int nv = 0;
#pragma unroll
    for (int i = 0; i < 32; ++i) {
        int c = i*32 + lane;
        float dx = __fadd_rn(qx, -sx[c]);
        float dy = __fadd_rn(qy, -sy[c]);
        float dz = __fadd_rn(qz, -sz[c]);
        float d2 = __fadd_rn(__fadd_rn(__fmul_rn(dx,dx), __fmul_rn(dy,dy)), __fmul_rn(dz,dz));
        bool v = (d2 <= R2);
        key[i] = v ? d2 : 1e10f;
        nv += v ? 1 : 0;
    }
    int total = nv;
#pragma unroll
    for (int off = 16; off > 0; off >>= 1) total += __shfl_xor_sync(0xffffffffu, total, off);

    int* my = d_nidx + p*KNB;
    if (total <= KNB) {
        int pos = 0;
#pragma unroll
        for (int i = 0; i < 32; ++i) {
            bool v = key[i] < 1e9f;
            unsigned m = __ballot_sync(0xffffffffu, v);
            if (v) my[pos + __popc(m & ((1u<<lane)-1u))] = i*32 + lane;
            pos += __popc(m);
        }
        for (int s = pos + lane; s < KNB; s += 32) my[s] = pl;  // padded slots: self
        if (lane == 0) d_ncnt[p] = total;
    } else {
        for (int s = 0; s < KNB; ++s) {
            float bv = 3e10f; int bi = 0x7fffffff;
#pragma unroll
            for (int i = 0; i < 32; ++i) {
                int c = i*32 + lane;
                if (key[i] < bv || (key[i] == bv && c < bi)) { bv = key[i]; bi = c; }
            }
#pragma unroll
            for (int off = 16; off > 0; off >>= 1) {
                float ov = __shfl_xor_sync(0xffffffffu, bv, off);
                int   oi = __shfl_xor_sync(0xffffffffu, bi, off);
                if (ov < bv || (ov == bv && oi < bi)) { bv = ov; bi = oi; }
            }
            if ((bi & 31) == lane) {
#pragma unroll
                for (int i = 0; i < 32; ++i) if (i*32 + lane == bi) key[i] = 2e10f;
            }
            if (lane == 0) my[s] = bi;
        }
        if (lane == 0) d_ncnt[p] = KNB;
    }
}

// ---------------- 4: x = feat@W_in+b ; q,k,v projections -------------------------
__global__ __launch_bounds__(96) void k_inproj(const float* __restrict__ Wi, const float* __restrict__ bi,
                                               const float* __restrict__ Wq, const float* __restrict__ Wk,
                                               const float* __restrict__ Wv) {
    __shared__ float sf[16][6];
    __shared__ float sx[16][96];
    const int t = threadIdx.x, r0 = blockIdx.x*16;
    {
        int r = t/6, j = t - r*6, row = r0 + r;
        sf[r][j] = (j < 3) ? d_color[row*3 + j] : d_coord[row*3 + j - 3];
    }
    __syncthreads();
    const int c = t;
    const float bc = bi[c];
#pragma unroll
    for (int r = 0; r < 16; ++r) {
        float a = bc;
#pragma unroll
        for (int j = 0; j < 6; ++j) a = __fmaf_rn(sf[r][j], Wi[j*96 + c], a);
        sx[r][c] = a;
        d_x[(r0 + r)*96 + c] = a;
    }
    __syncthreads();
    float aq[16], ak[16], av[16];
#pragma unroll
    for (int r = 0; r < 16; ++r) { aq[r] = 0.f; ak[r] = 0.f; av[r] = 0.f; }
    for (int j = 0; j < 96; ++j) {
        float wq = Wq[j*96 + c], wk = Wk[j*96 + c], wv = Wv[j*96 + c];
#pragma unroll
        for (int r = 0; r < 16; ++r) {
            float xv = sx[r][j];
            aq[r] = __fmaf_rn(xv, wq, aq[r]);
            ak[r] = __fmaf_rn(xv, wk, ak[r]);
            av[r] = __fmaf_rn(xv, wv, av[r]);
        }
    }
#pragma unroll
    for (int r = 0; r < 16; ++r) {
        d_qb[(r0 + r)*96 + c] = aq[r];
        d_kb[(r0 + r)*96 + c] = ak[r];
        d_vb[(r0 + r)*96 + c] = av[r];
    }
}

// ---------------- 5: local attention, one block per point ------------------------
__global__ __launch_bounds__(192) void k_attn(const float* __restrict__ Wpos) {
    const int p = blockIdx.x, pl = p & 1023, base = p - pl;
    const int t = threadIdx.x;
    __shared__ float sq[96];
    __shared__ float skn[KNB][96];
    __shared__ float svn[KNB][96];
    __shared__ float sdx[KNB], sdy[KNB], sdz[KNB];
    __shared__ int   snb[KNB];
    __shared__ float slog[HH*KNB];
    __shared__ int   scnt;

    if (t < KNB) {
        int nb = d_nidx[p*KNB + t];
        snb[t] = nb;
        int gn = base + nb;
        sdx[t] = __fadd_rn(d_coord[p*3+0], -d_coord[gn*3+0]);
        sdy[t] = __fadd_rn(d_coord[p*3+1], -d_coord[gn*3+1]);
        sdz[t] = __fadd_rn(d_coord[p*3+2], -d_coord[gn*3+2]);
    }
    if (t < 96) sq[t] = d_qb[p*96 + t];
    if (t == 0) scnt = d_ncnt[p];
    __syncthreads();

    for (int e = t; e < KNB*96; e += 192) {
        int kk = e / 96, c = e - kk*96;
        int gn = base + snb[kk];
        float pe = __fmaf_rn(sdz[kk], Wpos[192 + c],
                   __fmaf_rn(sdy[kk], Wpos[96 + c],
                   __fmul_rn(sdx[kk], Wpos[c])));
        skn[kk][c] = __fadd_rn(d_kb[gn*96 + c], pe);
        svn[kk][c] = __fadd_rn(d_vb[gn*96 + c], pe);
    }
    __syncthreads();

    const int cnt = scnt;
    for (int e = t; e < HH*KNB; e += 192) {
        int h = e / KNB, kk = e - h*KNB;
        float a = 0.f;
#pragma unroll
        for (int d = 0; d < 16; ++d) a = __fmaf_rn(sq[h*16 + d], skn[kk][h*16 + d], a);
        slog[h*KNB + kk] = (kk < cnt) ? __fmul_rn(a, 0.25f) : -1e9f;
    }
    __syncthreads();

    { // softmax: warp w == head w (6 warps exactly)
        int w = t >> 5, lane = t & 31;
        float v0 = slog[w*KNB + lane];
        float v1 = (lane < 2) ? slog[w*KNB + 32 + lane] : -3.0e38f;
        float m = fmaxf(v0, v1);
#pragma unroll
        for (int off = 16; off > 0; off >>= 1) m = fmaxf(m, __shfl_xor_sync(0xffffffffu, m, off));
        float e0 = expf(v0 - m);
        float e1 = (lane < 2) ? expf(v1 - m) : 0.f;
        float s = e0 + e1;
#pragma unroll
        for (int off = 16; off > 0; off >>= 1) s += __shfl_xor_sync(0xffffffffu, s, off);
        float inv = 1.0f / s;
        slog[w*KNB + lane] = e0 * inv;
        if (lane < 2) slog[w*KNB + 32 + lane] = e1 * inv;
    }
    __syncthreads();

    if (t < 96) {
        int h = t >> 4;
        float a = 0.f;
#pragma unroll
        for (int kk = 0; kk < KNB; ++kk) a = __fmaf_rn(slog[h*KNB + kk], svn[kk][t], a);
        d_ao[p*96 + t] = a;
    }
}

// ---------------- 6: x1 = LN(x + ao@Wo), one warp per row ------------------------
__global__ __launch_bounds__(256) void k_wo_ln(const float* __restrict__ Wo, const float* __restrict__ g1,
                                               const float* __restrict__ be1) {
    __shared__ float srow[8][96];
    const int w = threadIdx.x >> 5, lane = threadIdx.x & 31;
    const int r = blockIdx.x*8 + w;
    const int c0 = lane, c1 = lane + 32, c2 = lane + 64;
    srow[w][c0] = d_ao[r*96 + c0];
    srow[w][c1] = d_ao[r*96 + c1];
    srow[w][c2] = d_ao[r*96 + c2];
    float x0 = d_x[r*96 + c0], x1v = d_x[r*96 + c1], x2v = d_x[r*96 + c2];
    __syncwarp();
    float a0 = 0.f, a1 = 0.f, a2 = 0.f;
    for (int j = 0; j < 96; ++j) {
        float v = srow[w][j];
        a0 = __fmaf_rn(v, Wo[j*96 + c0], a0);
        a1 = __fmaf_rn(v, Wo[j*96 + c1], a1);
        a2 = __fmaf_rn(v, Wo[j*96 + c2], a2);
    }
    float y0 = __fadd_rn(x0, a0), y1 = __fadd_rn(x1v, a1), y2 = __fadd_rn(x2v, a2);
    float s = y0 + y1 + y2;
#pragma unroll
    for (int off = 16; off > 0; off >>= 1) s += __shfl_xor_sync(0xffffffffu, s, off);
    float m = s * (1.0f/96.0f);
    float d0 = y0 - m, d1 = y1 - m, d2 = y2 - m;
    float q = d0*d0 + d1*d1 + d2*d2;
#pragma unroll
    for (int off = 16; off > 0; off >>= 1) q += __shfl_xor_sync(0xffffffffu, q, off);
    float rs = rsqrtf(q*(1.0f/96.0f) + 1e-5f);
    d_x1[r*96 + c0] = __fmaf_rn(__fmul_rn(d0, rs), g1[c0], 0.f) + be1[c0];
    d_x1[r*96 + c1] = __fmaf_rn(__fmul_rn(d1, rs), g1[c1], 0.f) + be1[c1];
    d_x1[r*96 + c2] = __fmaf_rn(__fmul_rn(d2, rs), g1[c2], 0.f) + be1[c2];
}

// ---------------- 7: FFN + LN + transposed output --------------------------------
__global__ __launch_bounds__(384) void k_ffn(const float* __restrict__ W1, const float* __restrict__ b1,
                                             const float* __restrict__ W2, const float* __restrict__ b2,
                                             const float* __restrict__ g2, const float* __restrict__ be2,
                                             float* __restrict__ outF) {
    __shared__ float sx[16][96];
    __shared__ float sh[16][384];
    __shared__ float sy[16][96];
    __shared__ float sm[16], srs[16];
    const int t = threadIdx.x, r0 = blockIdx.x*16;

    for (int e = t; e < 16*96; e += 384) {
        int r = e / 96, c = e - r*96;
        sx[r][c] = d_x1[(r0 + r)*96 + c];
    }
    __syncthreads();
    { // hidden: col j = t
        int j = t;
        float acc[16];
        float bj = b1[j];
#pragma unroll
        for (int r = 0; r < 16; ++r) acc[r] = bj;
        for (int i = 0; i < 96; ++i) {
            float wv = W1[i*384 + j];
#pragma unroll
            for (int r = 0; r < 16; ++r) acc[r] = __fmaf_rn(sx[r][i], wv, acc[r]);
        }
#pragma unroll
        for (int r = 0; r < 16; ++r) sh[r][j] = fmaxf(acc[r], 0.f);
    }
    __syncthreads();
    { // output proj
        int g = t / 96, c = t - 96*g;
        float acc[4];
        float bc = b2[c];
#pragma unroll
        for (int rr = 0; rr < 4; ++rr) acc[rr] = bc;
        for (int j = 0; j < 384; ++j) {
            float wv = W2[j*96 + c];
#pragma unroll
            for (int rr = 0; rr < 4; ++rr) acc[rr] = __fmaf_rn(sh[g*4 + rr][j], wv, acc[rr]);
        }
#pragma unroll
        for (int rr = 0; rr < 4; ++rr) {
            int r = g*4 + rr;
            sy[r][c] = __fadd_rn(sx[r][c], acc[rr]);
        }
    }
    __syncthreads();
    if (t < 16) {
        float s = 0.f;
        for (int c = 0; c < 96; ++c) s += sy[t][c];
        float m = s * (1.0f/96.0f);
        float q = 0.f;
        for (int c = 0; c < 96; ++c) { float d = sy[t][c] - m; q += d*d; }
        sm[t] = m;
        srs[t] = rsqrtf(q*(1.0f/96.0f) + 1e-5f);
    }
    __syncthreads();
    {
        int g = t / 96, c = t - 96*g;
#pragma unroll
        for (int rr = 0; rr < 4; ++rr) {
            int r = g*4 + rr, row = r0 + r;
            float val = (sy[r][c] - sm[r]) * srs[r] * g2[c] + be2[c];
            int b = row >> 10, pl = row & 1023;
            outF[((long)b*96 + c)*1024 + pl] = val;
        }
    }
}

// ---------------- launch ----------------------------------------------------------
extern "C" void kernel_launch(void* const* d_in, const int* in_sizes, int n_in,
                              void* d_out, int out_size) {
    const float* pc   = (const float*)d_in[0];
    const float* col  = (const float*)d_in[1];
    const float* W_in = (const float*)d_in[2];
    const float* b_in = (const float*)d_in[3];
    const float* Wq   = (const float*)d_in[4];
    const float* Wk   = (const float*)d_in[5];
    const float* Wv   = (const float*)d_in[6];
    const float* Wo   = (const float*)d_in[7];
    const float* Wpos = (const float*)d_in[8];
    const float* W1   = (const float*)d_in[9];
    const float* b1   = (const float*)d_in[10];
    const float* W2   = (const float*)d_in[11];
    const float* b2   = (const float*)d_in[12];
    const float* g1   = (const float*)d_in[13];
    const float* be1  = (const float*)d_in[14];
    const float* g2   = (const float*)d_in[15];
    const float* be2  = (const float*)d_in[16];
    const int*   sel  = (const int*)d_in[17];
    float* out = (float*)d_out;

    k_transpose<<<(BB*NPAD + 255)/256, 256>>>(pc);
    k_fps<<<BB, 512>>>();
    k_gather<<<(NROWS + 255)/256, 256>>>(pc, col, sel, out + (long)BB*CC*NPT);
    k_neighbor<<<dim3(NPT/8, BB), 256>>>();
    k_inproj<<<NROWS/16, 96>>>(W_in, b_in, Wq, Wk, Wv);
    k_attn<<<NROWS, 192>>>(Wpos);
    k_wo_ln<<<NROWS/8, 256>>>(Wo, g1, be1);
    k_ffn<<<NROWS/16, 384>>>(W1, b1, W2, b2, g2, be2, out);
}

// round 14
// speedup vs baseline: 1.0704x; 1.0704x over previous
#include <cuda_runtime.h>

#define BB 8
#define N_IN 20000
#define NPAD 20480
#define N_ALL 1200
#define NPT 1024
#define KNB 34
#define CC 96
#define HH 6
#define NROWS (BB*NPT)

#define GPB 4            // CTAs per batch
#define FPS_T 512        // threads per FPS CTA
#define GT (GPB*FPS_T)   // 2048 threads per batch
#define PF2 5            // float2 pairs per thread: 10240 f2 / 2048 thr

// ---------------- scratch (device globals; no allocation allowed) ----------------
__device__ float d_xs[BB*NPAD];
__device__ float d_ys[BB*NPAD];
__device__ float d_zs[BB*NPAD];
__device__ int   d_fps[BB*N_ALL];
__device__ float d_coord[NROWS*3];
__device__ float d_color[NROWS*3];
__device__ int   d_nidx[NROWS*KNB];
__device__ int   d_ncnt[NROWS];
__device__ float d_x [NROWS*CC];
__device__ float d_qb[NROWS*CC];
__device__ float d_kb[NROWS*CC];
__device__ float d_vb[NROWS*CC];
__device__ float d_ao[NROWS*CC];
__device__ float d_x1[NROWS*CC];
__device__ float d_cand[BB*GPB*8];       // {val, idx-bits, x, y, z, pad...} per CTA
__device__ unsigned int d_bar[BB];       // monotonic arrival counter per batch

// ---------------- f32x2 helpers (per-lane rn: bit-identical to scalar) ------------
__device__ __forceinline__ unsigned long long f2pack(float a, float b) {
    unsigned long long r;
    asm("mov.b64 %0, {%1, %2};" : "=l"(r) : "f"(a), "f"(b));
    return r;
}
__device__ __forceinline__ void f2unpack(unsigned long long v, float& a, float& b) {
    asm("mov.b64 {%0, %1}, %2;" : "=f"(a), "=f"(b) : "l"(v));
}
__device__ __forceinline__ unsigned long long f2add(unsigned long long a, unsigned long long b) {
    unsigned long long r;
    asm("add.rn.f32x2 %0, %1, %2;" : "=l"(r) : "l"(a), "l"(b));
    return r;
}
__device__ __forceinline__ unsigned long long f2mul(unsigned long long a, unsigned long long b) {
    unsigned long long r;
    asm("mul.rn.f32x2 %0, %1, %2;" : "=l"(r) : "l"(a), "l"(b));
    return r;
}

// ---------------- 0: SoA transpose of point clouds (pad with point 0 clone) -------
__global__ void k_transpose(const float* __restrict__ pc) {
    int idx = blockIdx.x*blockDim.x + threadIdx.x;
    if (idx < BB) d_bar[idx] = 0u;                // reset FPS barrier each launch
    if (idx >= BB*NPAD) return;
    int b = idx / NPAD, i = idx - b*NPAD;
    int src = (i < N_IN) ? i : 0;                 // pad = clone of point 0 (dist->0, never argmax)
    const float* p = pc + ((long)b*N_IN + src)*3;
    d_xs[idx] = p[0]; d_ys[idx] = p[1]; d_zs[idx] = p[2];
}

// ---------------- 1: FPS — 4 CTAs per batch, coords in registers, L2 barrier ------
__global__ void __launch_bounds__(FPS_T, 1) k_fps() {
    const int b    = blockIdx.x >> 2;
    const int rank = blockIdx.x & 3;
    const int tid  = threadIdx.x;
    const int lane = tid & 31, wid = tid >> 5;
    const int g    = rank*FPS_T + tid;            // [0, 2048)

    // ---- load this thread's 10 points (5 float2 per dim) into registers ----
    unsigned long long X[PF2], Y[PF2], Z[PF2];
    {
        const float2* X2 = (const float2*)(d_xs + b*NPAD);
        const float2* Y2 = (const float2*)(d_ys + b*NPAD);
        const float2* Z2 = (const float2*)(d_zs + b*NPAD);
#pragma unroll
        for (int k = 0; k < PF2; ++k) {
            float2 xv = X2[k*GT + g], yv = Y2[k*GT + g], zv = Z2[k*GT + g];
            X[k] = f2pack(xv.x, xv.y);
            Y[k] = f2pack(yv.x, yv.y);
            Z[k] = f2pack(zv.x, zv.y);
        }
    }
    float dist[2*PF2];
#pragma unroll
    for (int i = 0; i < 2*PF2; ++i) dist[i] = 1e10f;

    __shared__ float s_val[16]; __shared__ int s_idx[16];
    __shared__ float s_wx[16], s_wy[16], s_wz[16];
    __shared__ float s_bc[3]; __shared__ int s_bci;

    volatile float*        my_cand = d_cand + (b*GPB + rank)*8;
    volatile unsigned int* bar     = d_bar + b;

    float cx = __ldg(d_xs + b*NPAD), cy = __ldg(d_ys + b*NPAD), cz = __ldg(d_zs + b*NPAD);
    int cur = 0;

    for (int t = 0; t < N_ALL; ++t) {
        if (rank == 0 && tid == 0) d_fps[b*N_ALL + t] = cur;

        unsigned long long ncx = f2pack(-cx, -cx);
        unsigned long long ncy = f2pack(-cy, -cy);
        unsigned long long ncz = f2pack(-cz, -cz);

        float best = -1.0f; int bidx = 0;
#pragma unroll
        for (int k = 0; k < PF2; ++k) {
            unsigned long long dx = f2add(X[k], ncx);
            unsigned long long dy = f2add(Y[k], ncy);
            unsigned long long dz = f2add(Z[k], ncz);
            // mul then summed adds (no fma) == reference elementwise lowering
            unsigned long long s = f2add(f2add(f2mul(dx,dx), f2mul(dy,dy)), f2mul(dz,dz));
            float lo, hi; f2unpack(s, lo, hi);
            float d0 = fminf(dist[2*k],   lo); dist[2*k]   = d0;
            float d1 = fminf(dist[2*k+1], hi); dist[2*k+1] = d1;
            int j0 = (k*GT + g)*2;
            if (d0 > best) { best = d0; bidx = j0;     }   // strict >: lowest index wins
            if (d1 > best) { best = d1; bidx = j0 + 1; }
        }

        // ---- warp butterfly argmax (all lanes converge on warp winner) ----
#pragma unroll
        for (int off = 16; off > 0; off >>= 1) {
            float ov = __shfl_xor_sync(0xffffffffu, best, off);
            int   oi = __shfl_xor_sync(0xffffffffu, bidx, off);
            if (ov > best || (ov == best && oi < bidx)) { best = ov; bidx = oi; }
        }
        // owner lane (winner is always within this warp) extracts its coords,
        // then broadcast via shuffle; lane 0 publishes to smem.
        {
            int owner = ((bidx >> 1) & (FPS_T - 1)) & 31;   // owner's lane in this warp
            int wk = bidx >> 12;                            // pair index 0..4
            int h  = bidx & 1;
            float wx = 0.f, wy = 0.f, wz = 0.f;
#pragma unroll
            for (int k2 = 0; k2 < PF2; ++k2) {
                if (k2 == wk) {
                    float a0, a1;
                    f2unpack(X[k2], a0, a1); wx = h ? a1 : a0;
                    f2unpack(Y[k2], a0, a1); wy = h ? a1 : a0;
                    f2unpack(Z[k2], a0, a1); wz = h ? a1 : a0;
                }
            }
            wx = __shfl_sync(0xffffffffu, wx, owner);
            wy = __shfl_sync(0xffffffffu, wy, owner);
            wz = __shfl_sync(0xffffffffu, wz, owner);
            if (lane == 0) {
                s_val[wid] = best; s_idx[wid] = bidx;
                s_wx[wid] = wx; s_wy[wid] = wy; s_wz[wid] = wz;
            }
        }
        __syncthreads();

        // ---- CTA reduce (warp 0) -> publish candidate + arrive ----
        if (wid == 0) {
            float v  = (lane < 16) ? s_val[lane] : -2.0f;
            int   i2 = (lane < 16) ? s_idx[lane] : 0x7fffffff;
            float xx = (lane < 16) ? s_wx[lane] : 0.f;
            float yy = (lane < 16) ? s_wy[lane] : 0.f;
            float zz = (lane < 16) ? s_wz[lane] : 0.f;
#pragma unroll
            for (int off = 8; off > 0; off >>= 1) {
                float ov = __shfl_xor_sync(0xffffffffu, v,  off);
                int   oi = __shfl_xor_sync(0xffffffffu, i2, off);
                float ox = __shfl_xor_sync(0xffffffffu, xx, off);
                float oy = __shfl_xor_sync(0xffffffffu, yy, off);
                float oz = __shfl_xor_sync(0xffffffffu, zz, off);
                if (ov > v || (ov == v && oi < i2)) { v = ov; i2 = oi; xx = ox; yy = oy; zz = oz; }
            }
            if (lane == 0) {
                my_cand[0] = v;
                my_cand[1] = __int_as_float(i2);
                my_cand[2] = xx; my_cand[3] = yy; my_cand[4] = zz;
                __threadfence();                        // make candidate visible before arrive
                atomicAdd((unsigned int*)bar, 1u);      // RED, no return
            }
        }

        // ---- wait for all 4 CTAs of this batch ----
        if (tid == 0) {
            unsigned int target = 4u*(unsigned)(t + 1);
            while (*bar < target) { }
        }
        __syncthreads();

        // ---- cross-CTA pick: lanes 0..3 of warp 0 read the 4 candidates ----
        if (wid == 0) {
            float v = -2.0f, xx = 0.f, yy = 0.f, zz = 0.f; int i2 = 0x7fffffff;
            if (lane < GPB) {
                volatile float* c = d_cand + (b*GPB + lane)*8;
                v  = c[0];
                i2 = __float_as_int(c[1]);
                xx = c[2]; yy = c[3]; zz = c[4];
            }
#pragma unroll
            for (int off = 2; off > 0; off >>= 1) {
                float ov = __shfl_xor_sync(0xffffffffu, v,  off);
                int   oi = __shfl_xor_sync(0xffffffffu, i2, off);
                float ox = __shfl_xor_sync(0xffffffffu, xx, off);
                float oy = __shfl_xor_sync(0xffffffffu, yy, off);
                float oz = __shfl_xor_sync(0xffffffffu, zz, off);
                if (ov > v || (ov == v && oi < i2)) { v = ov; i2 = oi; xx = ox; yy = oy; zz = oz; }
            }
            if (lane == 0) { s_bc[0] = xx; s_bc[1] = yy; s_bc[2] = zz; s_bci = i2; }
        }
        __syncthreads();
        cx = s_bc[0]; cy = s_bc[1]; cz = s_bc[2]; cur = s_bci;
    }
}

// ---------------- 2: gather selected points (fps_idx[:, sel]) --------------------
__global__ void k_gather(const float* __restrict__ pc, const float* __restrict__ col,
                         const int* __restrict__ sel, float* __restrict__ out_coord) {
    int p = blockIdx.x*blockDim.x + threadIdx.x;
    if (p >= NROWS) return;
    int b = p >> 10, i = p & 1023;
    int gi = d_fps[b*N_ALL + sel[i]];
    const float* s  = pc  + ((long)b*N_IN + gi)*3;
    const float* s2 = col + ((long)b*N_IN + gi)*3;
    d_coord[p*3+0] = s[0];  d_coord[p*3+1] = s[1];  d_coord[p*3+2] = s[2];
    d_color[p*3+0] = s2[0]; d_color[p*3+1] = s2[1]; d_color[p*3+2] = s2[2];
    out_coord[p*3+0] = s[0]; out_coord[p*3+1] = s[1]; out_coord[p*3+2] = s[2];
}

// ---------------- 3: radius neighbors, one warp per query point ------------------
__global__ __launch_bounds__(256) void k_neighbor() {
    __shared__ float sx[NPT], sy[NPT], sz[NPT];
    const int b = blockIdx.y;
    for (int i = threadIdx.x; i < NPT; i += 256) {
        const float* cp = d_coord + (b*NPT + i)*3;
        sx[i] = cp[0]; sy[i] = cp[1]; sz[i] = cp[2];
    }
    __syncthreads();
    const int warp = threadIdx.x >> 5, lane = threadIdx.x & 31;
    const int pl = blockIdx.x*8 + warp;
    const int p  = b*NPT + pl;
    const float qx = sx[pl], qy = sy[pl], qz = sz[pl];
    const float R2 = 0.010000000000000002f;
    float key[32];
    int nv = 0;
#pragma unroll
    for (int i = 0; i < 32; ++i) {
        int c = i*32 + lane;
        float dx = __fadd_rn(qx, -sx[c]);
        float dy = __fadd_rn(qy, -sy[c]);
        float dz = __fadd_rn(qz, -sz[c]);
        float d2 = __fadd_rn(__fadd_rn(__fmul_rn(dx,dx), __fmul_rn(dy,dy)), __fmul_rn(dz,dz));
        bool v = (d2 <= R2);
        key[i] = v ? d2 : 1e10f;
        nv += v ? 1 : 0;
    }
    int total = nv;
#pragma unroll
    for (int off = 16; off > 0; off >>= 1) total += __shfl_xor_sync(0xffffffffu, total, off);

    int* my = d_nidx + p*KNB;
    if (total <= KNB) {
        int pos = 0;
#pragma unroll
        for (int i = 0; i < 32; ++i) {
            bool v = key[i] < 1e9f;
            unsigned m = __ballot_sync(0xffffffffu, v);
            if (v) my[pos + __popc(m & ((1u<<lane)-1u))] = i*32 + lane;
            pos += __popc(m);
        }
        for (int s = pos + lane; s < KNB; s += 32) my[s] = pl;  // padded slots: self
        if (lane == 0) d_ncnt[p] = total;
    } else {
        for (int s = 0; s < KNB; ++s) {
            float bv = 3e10f; int bi = 0x7fffffff;
#pragma unroll
            for (int i = 0; i < 32; ++i) {
                int c = i*32 + lane;
                if (key[i] < bv || (key[i] == bv && c < bi)) { bv = key[i]; bi = c; }
            }
#pragma unroll
            for (int off = 16; off > 0; off >>= 1) {
                float ov = __shfl_xor_sync(0xffffffffu, bv, off);
                int   oi = __shfl_xor_sync(0xffffffffu, bi, off);
                if (ov < bv || (ov == bv && oi < bi)) { bv = ov; bi = oi; }
            }
            if ((bi & 31) == lane) {
#pragma unroll
                for (int i = 0; i < 32; ++i) if (i*32 + lane == bi) key[i] = 2e10f;
            }
            if (lane == 0) my[s] = bi;
        }
        if (lane == 0) d_ncnt[p] = KNB;
    }
}

// ---------------- 4: x = feat@W_in+b ; q,k,v projections -------------------------
__global__ __launch_bounds__(96) void k_inproj(const float* __restrict__ Wi, const float* __restrict__ bi,
                                               const float* __restrict__ Wq, const float* __restrict__ Wk,
                                               const float* __restrict__ Wv) {
    __shared__ float sf[16][6];
    __shared__ float sx[16][96];
    const int t = threadIdx.x, r0 = blockIdx.x*16;
    {
        int r = t/6, j = t - r*6, row = r0 + r;
        sf[r][j] = (j < 3) ? d_color[row*3 + j] : d_coord[row*3 + j - 3];
    }
    __syncthreads();
    const int c = t;
    const float bc = bi[c];
#pragma unroll
    for (int r = 0; r < 16; ++r) {
        float a = bc;
#pragma unroll
        for (int j = 0; j < 6; ++j) a = __fmaf_rn(sf[r][j], Wi[j*96 + c], a);
        sx[r][c] = a;
        d_x[(r0 + r)*96 + c] = a;
    }
    __syncthreads();
    float aq[16], ak[16], av[16];
#pragma unroll
    for (int r = 0; r < 16; ++r) { aq[r] = 0.f; ak[r] = 0.f; av[r] = 0.f; }
    for (int j = 0; j < 96; ++j) {
        float wq = Wq[j*96 + c], wk = Wk[j*96 + c], wv = Wv[j*96 + c];
#pragma unroll
        for (int r = 0; r < 16; ++r) {
            float xv = sx[r][j];
            aq[r] = __fmaf_rn(xv, wq, aq[r]);
            ak[r] = __fmaf_rn(xv, wk, ak[r]);
            av[r] = __fmaf_rn(xv, wv, av[r]);
        }
    }
#pragma unroll
    for (int r = 0; r < 16; ++r) {
        d_qb[(r0 + r)*96 + c] = aq[r];
        d_kb[(r0 + r)*96 + c] = ak[r];
        d_vb[(r0 + r)*96 + c] = av[r];
    }
}

// ---------------- 5: local attention, one block per point ------------------------
__global__ __launch_bounds__(192) void k_attn(const float* __restrict__ Wpos) {
    const int p = blockIdx.x, pl = p & 1023, base = p - pl;
    const int t = threadIdx.x;
    __shared__ float sq[96];
    __shared__ float skn[KNB][96];
    __shared__ float svn[KNB][96];
    __shared__ float sdx[KNB], sdy[KNB], sdz[KNB];
    __shared__ int   snb[KNB];
    __shared__ float slog[HH*KNB];
    __shared__ int   scnt;

    if (t < KNB) {
        int nb = d_nidx[p*KNB + t];
        snb[t] = nb;
        int gn = base + nb;
        sdx[t] = __fadd_rn(d_coord[p*3+0], -d_coord[gn*3+0]);
        sdy[t] = __fadd_rn(d_coord[p*3+1], -d_coord[gn*3+1]);
        sdz[t] = __fadd_rn(d_coord[p*3+2], -d_coord[gn*3+2]);
    }
    if (t < 96) sq[t] = d_qb[p*96 + t];
    if (t == 0) scnt = d_ncnt[p];
    __syncthreads();

    for (int e = t; e < KNB*96; e += 192) {
        int kk = e / 96, c = e - kk*96;
        int gn = base + snb[kk];
        float pe = __fmaf_rn(sdz[kk], Wpos[192 + c],
                   __fmaf_rn(sdy[kk], Wpos[96 + c],
                   __fmul_rn(sdx[kk], Wpos[c])));
        skn[kk][c] = __fadd_rn(d_kb[gn*96 + c], pe);
        svn[kk][c] = __fadd_rn(d_vb[gn*96 + c], pe);
    }
    __syncthreads();

    const int cnt = scnt;
    for (int e = t; e < HH*KNB; e += 192) {
        int h = e / KNB, kk = e - h*KNB;
        float a = 0.f;
#pragma unroll
        for (int d = 0; d < 16; ++d) a = __fmaf_rn(sq[h*16 + d], skn[kk][h*16 + d], a);
        slog[h*KNB + kk] = (kk < cnt) ? __fmul_rn(a, 0.25f) : -1e9f;
    }
    __syncthreads();

    { // softmax: warp w == head w (6 warps exactly)
        int w = t >> 5, lane = t & 31;
        float v0 = slog[w*KNB + lane];
        float v1 = (lane < 2) ? slog[w*KNB + 32 + lane] : -3.0e38f;
        float m = fmaxf(v0, v1);
#pragma unroll
        for (int off = 16; off > 0; off >>= 1) m = fmaxf(m, __shfl_xor_sync(0xffffffffu, m, off));
        float e0 = expf(v0 - m);
        float e1 = (lane < 2) ? expf(v1 - m) : 0.f;
        float s = e0 + e1;
#pragma unroll
        for (int off = 16; off > 0; off >>= 1) s += __shfl_xor_sync(0xffffffffu, s, off);
        float inv = 1.0f / s;
        slog[w*KNB + lane] = e0 * inv;
        if (lane < 2) slog[w*KNB + 32 + lane] = e1 * inv;
    }
    __syncthreads();

    if (t < 96) {
        int h = t >> 4;
        float a = 0.f;
#pragma unroll
        for (int kk = 0; kk < KNB; ++kk) a = __fmaf_rn(slog[h*KNB + kk], svn[kk][t], a);
        d_ao[p*96 + t] = a;
    }
}

// ---------------- 6: x1 = LN(x + ao@Wo), one warp per row ------------------------
__global__ __launch_bounds__(256) void k_wo_ln(const float* __restrict__ Wo, const float* __restrict__ g1,
                                               const float* __restrict__ be1) {
    __shared__ float srow[8][96];
    const int w = threadIdx.x >> 5, lane = threadIdx.x & 31;
    const int r = blockIdx.x*8 + w;
    const int c0 = lane, c1 = lane + 32, c2 = lane + 64;
    srow[w][c0] = d_ao[r*96 + c0];
    srow[w][c1] = d_ao[r*96 + c1];
    srow[w][c2] = d_ao[r*96 + c2];
    float x0 = d_x[r*96 + c0], x1v = d_x[r*96 + c1], x2v = d_x[r*96 + c2];
    __syncwarp();
    float a0 = 0.f, a1 = 0.f, a2 = 0.f;
    for (int j = 0; j < 96; ++j) {
        float v = srow[w][j];
        a0 = __fmaf_rn(v, Wo[j*96 + c0], a0);
        a1 = __fmaf_rn(v, Wo[j*96 + c1], a1);
        a2 = __fmaf_rn(v, Wo[j*96 + c2], a2);
    }
    float y0 = __fadd_rn(x0, a0), y1 = __fadd_rn(x1v, a1), y2 = __fadd_rn(x2v, a2);
    float s = y0 + y1 + y2;
#pragma unroll
    for (int off = 16; off > 0; off >>= 1) s += __shfl_xor_sync(0xffffffffu, s, off);
    float m = s * (1.0f/96.0f);
    float d0 = y0 - m, d1 = y1 - m, d2 = y2 - m;
    float q = d0*d0 + d1*d1 + d2*d2;
#pragma unroll
    for (int off = 16; off > 0; off >>= 1) q += __shfl_xor_sync(0xffffffffu, q, off);
    float rs = rsqrtf(q*(1.0f/96.0f) + 1e-5f);
    d_x1[r*96 + c0] = __fmaf_rn(__fmul_rn(d0, rs), g1[c0], 0.f) + be1[c0];
    d_x1[r*96 + c1] = __fmaf_rn(__fmul_rn(d1, rs), g1[c1], 0.f) + be1[c1];
    d_x1[r*96 + c2] = __fmaf_rn(__fmul_rn(d2, rs), g1[c2], 0.f) + be1[c2];
}

// ---------------- 7: FFN + LN + transposed output --------------------------------
__global__ __launch_bounds__(384) void k_ffn(const float* __restrict__ W1, const float* __restrict__ b1,
                                             const float* __restrict__ W2, const float* __restrict__ b2,
                                             const float* __restrict__ g2, const float* __restrict__ be2,
                                             float* __restrict__ outF) {
    __shared__ float sx[16][96];
    __shared__ float sh[16][384];
    __shared__ float sy[16][96];
    __shared__ float sm[16], srs[16];
    const int t = threadIdx.x, r0 = blockIdx.x*16;

    for (int e = t; e < 16*96; e += 384) {
        int r = e / 96, c = e - r*96;
        sx[r][c] = d_x1[(r0 + r)*96 + c];
    }
    __syncthreads();
    { // hidden: col j = t
        int j = t;
        float acc[16];
        float bj = b1[j];
#pragma unroll
        for (int r = 0; r < 16; ++r) acc[r] = bj;
        for (int i = 0; i < 96; ++i) {
            float wv = W1[i*384 + j];
#pragma unroll
            for (int r = 0; r < 16; ++r) acc[r] = __fmaf_rn(sx[r][i], wv, acc[r]);
        }
#pragma unroll
        for (int r = 0; r < 16; ++r) sh[r][j] = fmaxf(acc[r], 0.f);
    }
    __syncthreads();
    { // output proj
        int g = t / 96, c = t - 96*g;
        float acc[4];
        float bc = b2[c];
#pragma unroll
        for (int rr = 0; rr < 4; ++rr) acc[rr] = bc;
        for (int j = 0; j < 384; ++j) {
            float wv = W2[j*96 + c];
#pragma unroll
            for (int rr = 0; rr < 4; ++rr) acc[rr] = __fmaf_rn(sh[g*4 + rr][j], wv, acc[rr]);
        }
#pragma unroll
        for (int rr = 0; rr < 4; ++rr) {
            int r = g*4 + rr;
            sy[r][c] = __fadd_rn(sx[r][c], acc[rr]);
        }
    }
    __syncthreads();
    if (t < 16) {
        float s = 0.f;
        for (int c = 0; c < 96; ++c) s += sy[t][c];
        float m = s * (1.0f/96.0f);
        float q = 0.f;
        for (int c = 0; c < 96; ++c) { float d = sy[t][c] - m; q += d*d; }
        sm[t] = m;
        srs[t] = rsqrtf(q*(1.0f/96.0f) + 1e-5f);
    }
    __syncthreads();
    {
        int g = t / 96, c = t - 96*g;
#pragma unroll
        for (int rr = 0; rr < 4; ++rr) {
            int r = g*4 + rr, row = r0 + r;
            float val = (sy[r][c] - sm[r]) * srs[r] * g2[c] + be2[c];
            int b = row >> 10, pl = row & 1023;
            outF[((long)b*96 + c)*1024 + pl] = val;
        }
    }
}

// ---------------- launch ----------------------------------------------------------
extern "C" void kernel_launch(void* const* d_in, const int* in_sizes, int n_in,
                              void* d_out, int out_size) {
    const float* pc   = (const float*)d_in[0];
    const float* col  = (const float*)d_in[1];
    const float* W_in = (const float*)d_in[2];
    const float* b_in = (const float*)d_in[3];
    const float* Wq   = (const float*)d_in[4];
    const float* Wk   = (const float*)d_in[5];
    const float* Wv   = (const float*)d_in[6];
    const float* Wo   = (const float*)d_in[7];
    const float* Wpos = (const float*)d_in[8];
    const float* W1   = (const float*)d_in[9];
    const float* b1   = (const float*)d_in[10];
    const float* W2   = (const float*)d_in[11];
    const float* b2   = (const float*)d_in[12];
    const float* g1   = (const float*)d_in[13];
    const float* be1  = (const float*)d_in[14];
    const float* g2   = (const float*)d_in[15];
    const float* be2  = (const float*)d_in[16];
    const int*   sel  = (const int*)d_in[17];
    float* out = (float*)d_out;

    k_transpose<<<(BB*NPAD + 255)/256, 256>>>(pc);
    k_fps<<<BB*GPB, FPS_T>>>();
    k_gather<<<(NROWS + 255)/256, 256>>>(pc, col, sel, out + (long)BB*CC*NPT);
    k_neighbor<<<dim3(NPT/8, BB), 256>>>();
    k_inproj<<<NROWS/16, 96>>>(W_in, b_in, Wq, Wk, Wv);
    k_attn<<<NROWS, 192>>>(Wpos);
    k_wo_ln<<<NROWS/8, 256>>>(Wo, g1, be1);
    k_ffn<<<NROWS/16, 384>>>(W1, b1, W2, b2, g2, be2, out);
}

// round 16
// speedup vs baseline: 1.4698x; 1.3732x over previous
#include <cuda_runtime.h>

#define BB 8
#define N_IN 20000
#define NPAD 20480
#define N_ALL 1200
#define NPT 1024
#define KNB 34
#define CC 96
#define HH 6
#define NROWS (BB*NPT)

#define GPB 4            // CTAs per batch (cluster size)
#define FPS_T 512        // threads per FPS CTA
#define GT (GPB*FPS_T)   // 2048 threads per batch
#define PF2 5            // float2 pairs per thread: 10240 f2 / 2048 thr

// ---------------- scratch (device globals; no allocation allowed) ----------------
__device__ float d_xs[BB*NPAD];
__device__ float d_ys[BB*NPAD];
__device__ float d_zs[BB*NPAD];
__device__ int   d_fps[BB*N_ALL];
__device__ float d_coord[NROWS*3];
__device__ float d_color[NROWS*3];
__device__ int   d_nidx[NROWS*KNB];
__device__ int   d_ncnt[NROWS];
__device__ float d_x [NROWS*CC];
__device__ float d_qb[NROWS*CC];
__device__ float d_kb[NROWS*CC];
__device__ float d_vb[NROWS*CC];
__device__ float d_ao[NROWS*CC];
__device__ float d_x1[NROWS*CC];

// ---------------- f32x2 helpers (per-lane rn: bit-identical to scalar) ------------
__device__ __forceinline__ unsigned long long f2pack(float a, float b) {
    unsigned long long r;
    asm("mov.b64 %0, {%1, %2};" : "=l"(r) : "f"(a), "f"(b));
    return r;
}
__device__ __forceinline__ void f2unpack(unsigned long long v, float& a, float& b) {
    asm("mov.b64 {%0, %1}, %2;" : "=f"(a), "=f"(b) : "l"(v));
}
__device__ __forceinline__ unsigned long long f2add(unsigned long long a, unsigned long long b) {
    unsigned long long r;
    asm("add.rn.f32x2 %0, %1, %2;" : "=l"(r) : "l"(a), "l"(b));
    return r;
}
__device__ __forceinline__ unsigned long long f2mul(unsigned long long a, unsigned long long b) {
    unsigned long long r;
    asm("mul.rn.f32x2 %0, %1, %2;" : "=l"(r) : "l"(a), "l"(b));
    return r;
}
__device__ __forceinline__ unsigned int smem_u32(const void* p) {
    unsigned int a;
    asm("{ .reg .u64 t; cvta.to.shared.u64 t, %1; cvt.u32.u64 %0, t; }" : "=r"(a) : "l"(p));
    return a;
}

// ---------------- 0: SoA transpose of point clouds (pad with point 0 clone) -------
__global__ void k_transpose(const float* __restrict__ pc) {
    int idx = blockIdx.x*blockDim.x + threadIdx.x;
    if (idx >= BB*NPAD) return;
    int b = idx / NPAD, i = idx - b*NPAD;
    int src = (i < N_IN) ? i : 0;                 // pad = clone of point 0 (dist->0, never argmax)
    const float* p = pc + ((long)b*N_IN + src)*3;
    d_xs[idx] = p[0]; d_ys[idx] = p[1]; d_zs[idx] = p[2];
}

// ---------------- 1: FPS — 4-CTA cluster/batch, DSMEM mailboxes + local mbarrier --
__global__ void __cluster_dims__(GPB, 1, 1) __launch_bounds__(FPS_T, 1) k_fps() {
    const int b    = blockIdx.x >> 2;
    const int tid  = threadIdx.x;
    const int lane = tid & 31, wid = tid >> 5;
    unsigned int rank;
    asm("mov.u32 %0, %%cluster_ctarank;" : "=r"(rank));
    const int g = rank*FPS_T + tid;               // [0, 2048)

    // ---- load this thread's 10 points (5 float2 per dim) into registers ----
    unsigned long long X[PF2], Y[PF2], Z[PF2];
    {
        const float2* X2 = (const float2*)(d_xs + b*NPAD);
        const float2* Y2 = (const float2*)(d_ys + b*NPAD);
        const float2* Z2 = (const float2*)(d_zs + b*NPAD);
#pragma unroll
        for (int k = 0; k < PF2; ++k) {
            float2 xv = X2[k*GT + g], yv = Y2[k*GT + g], zv = Z2[k*GT + g];
            X[k] = f2pack(xv.x, xv.y);
            Y[k] = f2pack(yv.x, yv.y);
            Z[k] = f2pack(zv.x, zv.y);
        }
    }
    float dist[2*PF2];
#pragma unroll
    for (int i = 0; i < 2*PF2; ++i) dist[i] = 1e10f;

    __shared__ float s_val[16]; __shared__ int s_idx[16];
    __shared__ float s_wx[16], s_wy[16], s_wz[16];
    __shared__ __align__(16) float s_mail[2][GPB][8];   // [parity][src rank]{v,idx,x,y,z}
    __shared__ __align__(8)  unsigned long long s_mbar;
    __shared__ float s_bc[3]; __shared__ int s_bci;

    const unsigned int mbar_a = smem_u32(&s_mbar);
    unsigned int remMail[GPB], remBar[GPB];
    {
        const unsigned int mail_my = smem_u32(&s_mail[0][rank][0]);
#pragma unroll
        for (int r = 0; r < GPB; ++r) {
            asm("mapa.shared::cluster.u32 %0, %1, %2;" : "=r"(remMail[r]) : "r"(mail_my), "r"(r));
            asm("mapa.shared::cluster.u32 %0, %1, %2;" : "=r"(remBar[r])  : "r"(mbar_a),  "r"(r));
        }
    }

    if (tid == 0) {
        asm volatile("mbarrier.init.shared.b64 [%0], %1;" :: "r"(mbar_a), "r"(GPB) : "memory");
    }
    __syncthreads();
    // one-time cluster sync: all mbarriers initialized before any remote arrive
    asm volatile("barrier.cluster.arrive.aligned;" ::: "memory");
    asm volatile("barrier.cluster.wait.aligned;"   ::: "memory");

    float cx = __ldg(d_xs + b*NPAD), cy = __ldg(d_ys + b*NPAD), cz = __ldg(d_zs + b*NPAD);
    int cur = 0;

    for (int t = 0; t < N_ALL; ++t) {
        if (rank == 0 && tid == 0) d_fps[b*N_ALL + t] = cur;

        unsigned long long ncx = f2pack(-cx, -cx);
        unsigned long long ncy = f2pack(-cy, -cy);
        unsigned long long ncz = f2pack(-cz, -cz);

        float best = -1.0f; int bidx = 0;
#pragma unroll
        for (int k = 0; k < PF2; ++k) {
            unsigned long long dx = f2add(X[k], ncx);
            unsigned long long dy = f2add(Y[k], ncy);
            unsigned long long dz = f2add(Z[k], ncz);
            // mul then summed adds (no fma) == reference elementwise lowering
            unsigned long long s = f2add(f2add(f2mul(dx,dx), f2mul(dy,dy)), f2mul(dz,dz));
            float lo, hi; f2unpack(s, lo, hi);
            float d0 = fminf(dist[2*k],   lo); dist[2*k]   = d0;
            float d1 = fminf(dist[2*k+1], hi); dist[2*k+1] = d1;
            int j0 = (k*GT + g)*2;
            if (d0 > best) { best = d0; bidx = j0;     }   // strict >: lowest index wins
            if (d1 > best) { best = d1; bidx = j0 + 1; }
        }

        // ---- warp butterfly argmax (all lanes converge on warp winner) ----
#pragma unroll
        for (int off = 16; off > 0; off >>= 1) {
            float ov = __shfl_xor_sync(0xffffffffu, best, off);
            int   oi = __shfl_xor_sync(0xffffffffu, bidx, off);
            if (ov > best || (ov == best && oi < bidx)) { best = ov; bidx = oi; }
        }
        // owner lane extracts winner coords; broadcast via shuffle; lane0 publishes
        {
            int owner = ((bidx >> 1) & (FPS_T - 1)) & 31;   // owner's lane in this warp
            int wk = bidx >> 12;                            // pair index 0..4
            int h  = bidx & 1;
            float wx = 0.f, wy = 0.f, wz = 0.f;
#pragma unroll
            for (int k2 = 0; k2 < PF2; ++k2) {
                if (k2 == wk) {
                    float a0, a1;
                    f2unpack(X[k2], a0, a1); wx = h ? a1 : a0;
                    f2unpack(Y[k2], a0, a1); wy = h ? a1 : a0;
                    f2unpack(Z[k2], a0, a1); wz = h ? a1 : a0;
                }
            }
            wx = __shfl_sync(0xffffffffu, wx, owner);
            wy = __shfl_sync(0xffffffffu, wy, owner);
            wz = __shfl_sync(0xffffffffu, wz, owner);
            if (lane == 0) {
                s_val[wid] = best; s_idx[wid] = bidx;
                s_wx[wid] = wx; s_wy[wid] = wy; s_wz[wid] = wz;
            }
        }
        __syncthreads();

        if (wid == 0) {
            // ---- CTA reduce over 16 warp winners ----
            float v  = (lane < 16) ? s_val[lane] : -2.0f;
            int   i2 = (lane < 16) ? s_idx[lane] : 0x7fffffff;
            float xx = (lane < 16) ? s_wx[lane] : 0.f;
            float yy = (lane < 16) ? s_wy[lane] : 0.f;
            float zz = (lane < 16) ? s_wz[lane] : 0.f;
#pragma unroll
            for (int off = 8; off > 0; off >>= 1) {
                float ov = __shfl_xor_sync(0xffffffffu, v,  off);
                int   oi = __shfl_xor_sync(0xffffffffu, i2, off);
                float ox = __shfl_xor_sync(0xffffffffu, xx, off);
                float oy = __shfl_xor_sync(0xffffffffu, yy, off);
                float oz = __shfl_xor_sync(0xffffffffu, zz, off);
                if (ov > v || (ov == v && oi < i2)) { v = ov; i2 = oi; xx = ox; yy = oy; zz = oz; }
            }
            // ---- publish candidate to all 4 CTAs' mailboxes (double-buffered) ----
            const unsigned int off_p = (unsigned)(t & 1) * (GPB*8*4);
            if (lane == 0) {
#pragma unroll
                for (int r = 0; r < GPB; ++r) {
                    asm volatile("st.shared::cluster.v4.f32 [%0], {%1,%2,%3,%4};"
                                 :: "r"(remMail[r] + off_p), "f"(v), "f"(__int_as_float(i2)),
                                    "f"(xx), "f"(yy) : "memory");
                    asm volatile("st.shared::cluster.f32 [%0], %1;"
                                 :: "r"(remMail[r] + off_p + 16), "f"(zz) : "memory");
                }
                asm volatile("fence.acq_rel.cluster;" ::: "memory");
#pragma unroll
                for (int r = 0; r < GPB; ++r)
                    asm volatile("mbarrier.arrive.shared::cluster.b64 _, [%0];"
                                 :: "r"(remBar[r]) : "memory");
            }
            // ---- wait local mbarrier: all 4 arrivals of this iteration ----
            {
                const unsigned int parity = (unsigned)(t & 1);
                unsigned int done;
                asm volatile(
                    "{\n\t.reg .pred p;\n\t"
                    "mbarrier.try_wait.parity.acquire.cta.shared::cta.b64 p, [%1], %2;\n\t"
                    "selp.b32 %0, 1, 0, p;\n\t}"
                    : "=r"(done) : "r"(mbar_a), "r"(parity) : "memory");
                if (!done) {
                    asm volatile(
                        "{\n\t.reg .pred P1;\n\t"
                        "WL_%=:\n\t"
                        "mbarrier.try_wait.parity.acquire.cta.shared::cta.b64 P1, [%0], %1, 0x989680;\n\t"
                        "@P1 bra.uni WD_%=;\n\t"
                        "bra.uni WL_%=;\n\t"
                        "WD_%=:\n\t}"
                        :: "r"(mbar_a), "r"(parity) : "memory");
                }
                asm volatile("fence.acq_rel.cluster;" ::: "memory");
            }
            // ---- pick across the 4 candidates (local smem now) ----
            {
                float vv = -2.0f, xx2 = 0.f, yy2 = 0.f, zz2 = 0.f; int ii = 0x7fffffff;
                if (lane < GPB) {
                    const float* c = &s_mail[t & 1][lane][0];
                    vv = c[0]; ii = __float_as_int(c[1]);
                    xx2 = c[2]; yy2 = c[3]; zz2 = c[4];
                }
#pragma unroll
                for (int off = 2; off > 0; off >>= 1) {
                    float ov = __shfl_xor_sync(0xffffffffu, vv,  off);
                    int   oi = __shfl_xor_sync(0xffffffffu, ii,  off);
                    float ox = __shfl_xor_sync(0xffffffffu, xx2, off);
                    float oy = __shfl_xor_sync(0xffffffffu, yy2, off);
                    float oz = __shfl_xor_sync(0xffffffffu, zz2, off);
                    if (ov > vv || (ov == vv && oi < ii)) { vv = ov; ii = oi; xx2 = ox; yy2 = oy; zz2 = oz; }
                }
                if (lane == 0) { s_bc[0] = xx2; s_bc[1] = yy2; s_bc[2] = zz2; s_bci = ii; }
            }
        }
        __syncthreads();
        cx = s_bc[0]; cy = s_bc[1]; cz = s_bc[2]; cur = s_bci;
    }
}

// ---------------- 2: gather selected points (fps_idx[:, sel]) --------------------
__global__ void k_gather(const float* __restrict__ pc, const float* __restrict__ col,
                         const int* __restrict__ sel, float* __restrict__ out_coord) {
    int p = blockIdx.x*blockDim.x + threadIdx.x;
    if (p >= NROWS) return;
    int b = p >> 10, i = p & 1023;
    int gi = d_fps[b*N_ALL + sel[i]];
    const float* s  = pc  + ((long)b*N_IN + gi)*3;
    const float* s2 = col + ((long)b*N_IN + gi)*3;
    d_coord[p*3+0] = s[0];  d_coord[p*3+1] = s[1];  d_coord[p*3+2] = s[2];
    d_color[p*3+0] = s2[0]; d_color[p*3+1] = s2[1]; d_color[p*3+2] = s2[2];
    out_coord[p*3+0] = s[0]; out_coord[p*3+1] = s[1]; out_coord[p*3+2] = s[2];
}

// ---------------- 3: radius neighbors, one warp per query point ------------------
__global__ __launch_bounds__(256) void k_neighbor() {
    __shared__ float sx[NPT], sy[NPT], sz[NPT];
    const int b = blockIdx.y;
    for (int i = threadIdx.x; i < NPT; i += 256) {
        const float* cp = d_coord + (b*NPT + i)*3;
        sx[i] = cp[0]; sy[i] = cp[1]; sz[i] = cp[2];
    }
    __syncthreads();
    const int warp = threadIdx.x >> 5, lane = threadIdx.x & 31;
    const int pl = blockIdx.x*8 + warp;
    const int p  = b*NPT + pl;
    const float qx = sx[pl], qy = sy[pl], qz = sz[pl];
    const float R2 = 0.010000000000000002f;
    float key[32];
    int nv = 0;
#pragma unroll
    for (int i = 0; i < 32; ++i) {
        int c = i*32 + lane;
        float dx = __fadd_rn(qx, -sx[c]);
        float dy = __fadd_rn(qy, -sy[c]);
        float dz = __fadd_rn(qz, -sz[c]);
        float d2 = __fadd_rn(__fadd_rn(__fmul_rn(dx,dx), __fmul_rn(dy,dy)), __fmul_rn(dz,dz));
        bool v = (d2 <= R2);
        key[i] = v ? d2 : 1e10f;
        nv += v ? 1 : 0;
    }
    int total = nv;
#pragma unroll
    for (int off = 16; off > 0; off >>= 1) total += __shfl_xor_sync(0xffffffffu, total, off);

    int* my = d_nidx + p*KNB;
    if (total <= KNB) {
        int pos = 0;
#pragma unroll
        for (int i = 0; i < 32; ++i) {
            bool v = key[i] < 1e9f;
            unsigned m = __ballot_sync(0xffffffffu, v);
            if (v) my[pos + __popc(m & ((1u<<lane)-1u))] = i*32 + lane;
            pos += __popc(m);
        }
        for (int s = pos + lane; s < KNB; s += 32) my[s] = pl;  // padded slots: self
        if (lane == 0) d_ncnt[p] = total;
    } else {
        for (int s = 0; s < KNB; ++s) {
            float bv = 3e10f; int bi = 0x7fffffff;
#pragma unroll
            for (int i = 0; i < 32; ++i) {
                int c = i*32 + lane;
                if (key[i] < bv || (key[i] == bv && c < bi)) { bv = key[i]; bi = c; }
            }
#pragma unroll
            for (int off = 16; off > 0; off >>= 1) {
                float ov = __shfl_xor_sync(0xffffffffu, bv, off);
                int   oi = __shfl_xor_sync(0xffffffffu, bi, off);
                if (ov < bv || (ov == bv && oi < bi)) { bv = ov; bi = oi; }
            }
            if ((bi & 31) == lane) {
#pragma unroll
                for (int i = 0; i < 32; ++i) if (i*32 + lane == bi) key[i] = 2e10f;
            }
            if (lane == 0) my[s] = bi;
        }
        if (lane == 0) d_ncnt[p] = KNB;
    }
}

// ---------------- 4: x = feat@W_in+b ; q,k,v projections -------------------------
__global__ __launch_bounds__(96) void k_inproj(const float* __restrict__ Wi, const float* __restrict__ bi,
                                               const float* __restrict__ Wq, const float* __restrict__ Wk,
                                               const float* __restrict__ Wv) {
    __shared__ float sf[16][6];
    __shared__ float sx[16][96];
    const int t = threadIdx.x, r0 = blockIdx.x*16;
    {
        int r = t/6, j = t - r*6, row = r0 + r;
        sf[r][j] = (j < 3) ? d_color[row*3 + j] : d_coord[row*3 + j - 3];
    }
    __syncthreads();
    const int c = t;
    const float bc = bi[c];
#pragma unroll
    for (int r = 0; r < 16; ++r) {
        float a = bc;
#pragma unroll
        for (int j = 0; j < 6; ++j) a = __fmaf_rn(sf[r][j], Wi[j*96 + c], a);
        sx[r][c] = a;
        d_x[(r0 + r)*96 + c] = a;
    }
    __syncthreads();
    float aq[16], ak[16], av[16];
#pragma unroll
    for (int r = 0; r < 16; ++r) { aq[r] = 0.f; ak[r] = 0.f; av[r] = 0.f; }
    for (int j = 0; j < 96; ++j) {
        float wq = Wq[j*96 + c], wk = Wk[j*96 + c], wv = Wv[j*96 + c];
#pragma unroll
        for (int r = 0; r < 16; ++r) {
            float xv = sx[r][j];
            aq[r] = __fmaf_rn(xv, wq, aq[r]);
            ak[r] = __fmaf_rn(xv, wk, ak[r]);
            av[r] = __fmaf_rn(xv, wv, av[r]);
        }
    }
#pragma unroll
    for (int r = 0; r < 16; ++r) {
        d_qb[(r0 + r)*96 + c] = aq[r];
        d_kb[(r0 + r)*96 + c] = ak[r];
        d_vb[(r0 + r)*96 + c] = av[r];
    }
}

// ---------------- 5: local attention, one block per point ------------------------
__global__ __launch_bounds__(192) void k_attn(const float* __restrict__ Wpos) {
    const int p = blockIdx.x, pl = p & 1023, base = p - pl;
    const int t = threadIdx.x;
    __shared__ float sq[96];
    __shared__ float skn[KNB][96];
    __shared__ float svn[KNB][96];
    __shared__ float sdx[KNB], sdy[KNB], sdz[KNB];
    __shared__ int   snb[KNB];
    __shared__ float slog[HH*KNB];
    __shared__ int   scnt;

    if (t < KNB) {
        int nb = d_nidx[p*KNB + t];
        snb[t] = nb;
        int gn = base + nb;
        sdx[t] = __fadd_rn(d_coord[p*3+0], -d_coord[gn*3+0]);
        sdy[t] = __fadd_rn(d_coord[p*3+1], -d_coord[gn*3+1]);
        sdz[t] = __fadd_rn(d_coord[p*3+2], -d_coord[gn*3+2]);
    }
    if (t < 96) sq[t] = d_qb[p*96 + t];
    if (t == 0) scnt = d_ncnt[p];
    __syncthreads();

    for (int e = t; e < KNB*96; e += 192) {
        int kk = e / 96, c = e - kk*96;
        int gn = base + snb[kk];
        float pe = __fmaf_rn(sdz[kk], Wpos[192 + c],
                   __fmaf_rn(sdy[kk], Wpos[96 + c],
                   __fmul_rn(sdx[kk], Wpos[c])));
        skn[kk][c] = __fadd_rn(d_kb[gn*96 + c], pe);
        svn[kk][c] = __fadd_rn(d_vb[gn*96 + c], pe);
    }
    __syncthreads();

    const int cnt = scnt;
    for (int e = t; e < HH*KNB; e += 192) {
        int h = e / KNB, kk = e - h*KNB;
        float a = 0.f;
#pragma unroll
        for (int d = 0; d < 16; ++d) a = __fmaf_rn(sq[h*16 + d], skn[kk][h*16 + d], a);
        slog[h*KNB + kk] = (kk < cnt) ? __fmul_rn(a, 0.25f) : -1e9f;
    }
    __syncthreads();

    { // softmax: warp w == head w (6 warps exactly)
        int w = t >> 5, lane = t & 31;
        float v0 = slog[w*KNB + lane];
        float v1 = (lane < 2) ? slog[w*KNB + 32 + lane] : -3.0e38f;
        float m = fmaxf(v0, v1);
#pragma unroll
        for (int off = 16; off > 0; off >>= 1) m = fmaxf(m, __shfl_xor_sync(0xffffffffu, m, off));
        float e0 = expf(v0 - m);
        float e1 = (lane < 2) ? expf(v1 - m) : 0.f;
        float s = e0 + e1;
#pragma unroll
        for (int off = 16; off > 0; off >>= 1) s += __shfl_xor_sync(0xffffffffu, s, off);
        float inv = 1.0f / s;
        slog[w*KNB + lane] = e0 * inv;
        if (lane < 2) slog[w*KNB + 32 + lane] = e1 * inv;
    }
    __syncthreads();

    if (t < 96) {
        int h = t >> 4;
        float a = 0.f;
#pragma unroll
        for (int kk = 0; kk < KNB; ++kk) a = __fmaf_rn(slog[h*KNB + kk], svn[kk][t], a);
        d_ao[p*96 + t] = a;
    }
}

// ---------------- 6: x1 = LN(x + ao@Wo), one warp per row ------------------------
__global__ __launch_bounds__(256) void k_wo_ln(const float* __restrict__ Wo, const float* __restrict__ g1,
                                               const float* __restrict__ be1) {
    __shared__ float srow[8][96];
    const int w = threadIdx.x >> 5, lane = threadIdx.x & 31;
    const int r = blockIdx.x*8 + w;
    const int c0 = lane, c1 = lane + 32, c2 = lane + 64;
    srow[w][c0] = d_ao[r*96 + c0];
    srow[w][c1] = d_ao[r*96 + c1];
    srow[w][c2] = d_ao[r*96 + c2];
    float x0 = d_x[r*96 + c0], x1v = d_x[r*96 + c1], x2v = d_x[r*96 + c2];
    __syncwarp();
    float a0 = 0.f, a1 = 0.f, a2 = 0.f;
    for (int j = 0; j < 96; ++j) {
        float v = srow[w][j];
        a0 = __fmaf_rn(v, Wo[j*96 + c0], a0);
        a1 = __fmaf_rn(v, Wo[j*96 + c1], a1);
        a2 = __fmaf_rn(v, Wo[j*96 + c2], a2);
    }
    float y0 = __fadd_rn(x0, a0), y1 = __fadd_rn(x1v, a1), y2 = __fadd_rn(x2v, a2);
    float s = y0 + y1 + y2;
#pragma unroll
    for (int off = 16; off > 0; off >>= 1) s += __shfl_xor_sync(0xffffffffu, s, off);
    float m = s * (1.0f/96.0f);
    float d0 = y0 - m, d1 = y1 - m, d2 = y2 - m;
    float q = d0*d0 + d1*d1 + d2*d2;
#pragma unroll
    for (int off = 16; off > 0; off >>= 1) q += __shfl_xor_sync(0xffffffffu, q, off);
    float rs = rsqrtf(q*(1.0f/96.0f) + 1e-5f);
    d_x1[r*96 + c0] = __fmaf_rn(__fmul_rn(d0, rs), g1[c0], 0.f) + be1[c0];
    d_x1[r*96 + c1] = __fmaf_rn(__fmul_rn(d1, rs), g1[c1], 0.f) + be1[c1];
    d_x1[r*96 + c2] = __fmaf_rn(__fmul_rn(d2, rs), g1[c2], 0.f) + be1[c2];
}

// ---------------- 7: FFN + LN + transposed output --------------------------------
__global__ __launch_bounds__(384) void k_ffn(const float* __restrict__ W1, const float* __restrict__ b1,
                                             const float* __restrict__ W2, const float* __restrict__ b2,
                                             const float* __restrict__ g2, const float* __restrict__ be2,
                                             float* __restrict__ outF) {
    __shared__ float sx[16][96];
    __shared__ float sh[16][384];
    __shared__ float sy[16][96];
    __shared__ float sm[16], srs[16];
    const int t = threadIdx.x, r0 = blockIdx.x*16;

    for (int e = t; e < 16*96; e += 384) {
        int r = e / 96, c = e - r*96;
        sx[r][c] = d_x1[(r0 + r)*96 + c];
    }
    __syncthreads();
    { // hidden: col j = t
        int j = t;
        float acc[16];
        float bj = b1[j];
#pragma unroll
        for (int r = 0; r < 16; ++r) acc[r] = bj;
        for (int i = 0; i < 96; ++i) {
            float wv = W1[i*384 + j];
#pragma unroll
            for (int r = 0; r < 16; ++r) acc[r] = __fmaf_rn(sx[r][i], wv, acc[r]);
        }
#pragma unroll
        for (int r = 0; r < 16; ++r) sh[r][j] = fmaxf(acc[r], 0.f);
    }
    __syncthreads();
    { // output proj
        int g = t / 96, c = t - 96*g;
        float acc[4];
        float bc = b2[c];
#pragma unroll
        for (int rr = 0; rr < 4; ++rr) acc[rr] = bc;
        for (int j = 0; j < 384; ++j) {
            float wv = W2[j*96 + c];
#pragma unroll
            for (int rr = 0; rr < 4; ++rr) acc[rr] = __fmaf_rn(sh[g*4 + rr][j], wv, acc[rr]);
        }
#pragma unroll
        for (int rr = 0; rr < 4; ++rr) {
            int r = g*4 + rr;
            sy[r][c] = __fadd_rn(sx[r][c], acc[rr]);
        }
    }
    __syncthreads();
    if (t < 16) {
        float s = 0.f;
        for (int c = 0; c < 96; ++c) s += sy[t][c];
        float m = s * (1.0f/96.0f);
        float q = 0.f;
        for (int c = 0; c < 96; ++c) { float d = sy[t][c] - m; q += d*d; }
        sm[t] = m;
        srs[t] = rsqrtf(q*(1.0f/96.0f) + 1e-5f);
    }
    __syncthreads();
    {
        int g = t / 96, c = t - 96*g;
#pragma unroll
        for (int rr = 0; rr < 4; ++rr) {
            int r = g*4 + rr, row = r0 + r;
            float val = (sy[r][c] - sm[r]) * srs[r] * g2[c] + be2[c];
            int b = row >> 10, pl = row & 1023;
            outF[((long)b*96 + c)*1024 + pl] = val;
        }
    }
}

// ---------------- launch ----------------------------------------------------------
extern "C" void kernel_launch(void* const* d_in, const int* in_sizes, int n_in,
                              void* d_out, int out_size) {
    const float* pc   = (const float*)d_in[0];
    const float* col  = (const float*)d_in[1];
    const float* W_in = (const float*)d_in[2];
    const float* b_in = (const float*)d_in[3];
    const float* Wq   = (const float*)d_in[4];
    const float* Wk   = (const float*)d_in[5];
    const float* Wv   = (const float*)d_in[6];
    const float* Wo   = (const float*)d_in[7];
    const float* Wpos = (const float*)d_in[8];
    const float* W1   = (const float*)d_in[9];
    const float* b1   = (const float*)d_in[10];
    const float* W2   = (const float*)d_in[11];
    const float* b2   = (const float*)d_in[12];
    const float* g1   = (const float*)d_in[13];
    const float* be1  = (const float*)d_in[14];
    const float* g2   = (const float*)d_in[15];
    const float* be2  = (const float*)d_in[16];
    const int*   sel  = (const int*)d_in[17];
    float* out = (float*)d_out;

    k_transpose<<<(BB*NPAD + 255)/256, 256>>>(pc);
    k_fps<<<BB*GPB, FPS_T>>>();
    k_gather<<<(NROWS + 255)/256, 256>>>(pc, col, sel, out + (long)BB*CC*NPT);
    k_neighbor<<<dim3(NPT/8, BB), 256>>>();
    k_inproj<<<NROWS/16, 96>>>(W_in, b_in, Wq, Wk, Wv);
    k_attn<<<NROWS, 192>>>(Wpos);
    k_wo_ln<<<NROWS/8, 256>>>(Wo, g1, be1);
    k_ffn<<<NROWS/16, 384>>>(W1, b1, W2, b2, g2, be2, out);
}

// round 17
// speedup vs baseline: 1.7468x; 1.1884x over previous
#include <cuda_runtime.h>

#define BB 8
#define N_IN 20000
#define NPAD 20480
#define N_ALL 1200
#define NPT 1024
#define KNB 34
#define CC 96
#define HH 6
#define NROWS (BB*NPT)

#define GPB 8            // CTAs per batch (cluster size)
#define FPS_T 256        // threads per FPS CTA
#define GT (GPB*FPS_T)   // 2048 threads per batch (same as before)
#define PF2 5            // float2 pairs per thread: 10240 f2 / 2048 thr
#define NWARP (FPS_T/32) // 8 warps per CTA

// ---------------- scratch (device globals; no allocation allowed) ----------------
__device__ float d_xs[BB*NPAD];
__device__ float d_ys[BB*NPAD];
__device__ float d_zs[BB*NPAD];
__device__ int   d_fps[BB*N_ALL];
__device__ float d_coord[NROWS*3];
__device__ float d_color[NROWS*3];
__device__ int   d_nidx[NROWS*KNB];
__device__ int   d_ncnt[NROWS];
__device__ float d_x [NROWS*CC];
__device__ float d_qb[NROWS*CC];
__device__ float d_kb[NROWS*CC];
__device__ float d_vb[NROWS*CC];
__device__ float d_ao[NROWS*CC];
__device__ float d_x1[NROWS*CC];

// ---------------- f32x2 helpers (per-lane rn: bit-identical to scalar) ------------
__device__ __forceinline__ unsigned long long f2pack(float a, float b) {
    unsigned long long r;
    asm("mov.b64 %0, {%1, %2};" : "=l"(r) : "f"(a), "f"(b));
    return r;
}
__device__ __forceinline__ void f2unpack(unsigned long long v, float& a, float& b) {
    asm("mov.b64 {%0, %1}, %2;" : "=f"(a), "=f"(b) : "l"(v));
}
__device__ __forceinline__ unsigned long long f2add(unsigned long long a, unsigned long long b) {
    unsigned long long r;
    asm("add.rn.f32x2 %0, %1, %2;" : "=l"(r) : "l"(a), "l"(b));
    return r;
}
__device__ __forceinline__ unsigned long long f2mul(unsigned long long a, unsigned long long b) {
    unsigned long long r;
    asm("mul.rn.f32x2 %0, %1, %2;" : "=l"(r) : "l"(a), "l"(b));
    return r;
}
__device__ __forceinline__ unsigned int smem_u32(const void* p) {
    unsigned int a;
    asm("{ .reg .u64 t; cvta.to.shared.u64 t, %1; cvt.u32.u64 %0, t; }" : "=r"(a) : "l"(p));
    return a;
}
__device__ __forceinline__ unsigned int redux_max_u32(unsigned int v) {
    unsigned int r;
    asm("redux.sync.max.u32 %0, %1, 0xffffffff;" : "=r"(r) : "r"(v));
    return r;
}
__device__ __forceinline__ unsigned int redux_min_u32(unsigned int v) {
    unsigned int r;
    asm("redux.sync.min.u32 %0, %1, 0xffffffff;" : "=r"(r) : "r"(v));
    return r;
}

// ---------------- 0: SoA transpose of point clouds (pad with point 0 clone) -------
__global__ void k_transpose(const float* __restrict__ pc) {
    int idx = blockIdx.x*blockDim.x + threadIdx.x;
    if (idx >= BB*NPAD) return;
    int b = idx / NPAD, i = idx - b*NPAD;
    int src = (i < N_IN) ? i : 0;                 // pad = clone of point 0 (dist->0, never argmax)
    const float* p = pc + ((long)b*N_IN + src)*3;
    d_xs[idx] = p[0]; d_ys[idx] = p[1]; d_zs[idx] = p[2];
}

// ---------------- 1: FPS — 8-CTA cluster/batch, redux argmax, DSMEM mailboxes -----
__global__ void __cluster_dims__(GPB, 1, 1) __launch_bounds__(FPS_T, 1) k_fps() {
    const int b    = blockIdx.x / GPB;
    const int tid  = threadIdx.x;
    const int lane = tid & 31, wid = tid >> 5;
    unsigned int rank;
    asm("mov.u32 %0, %%cluster_ctarank;" : "=r"(rank));
    const int g = rank*FPS_T + tid;               // [0, 2048)

    // ---- load this thread's 10 points (5 float2 per dim) into registers ----
    unsigned long long X[PF2], Y[PF2], Z[PF2];
    {
        const float2* X2 = (const float2*)(d_xs + b*NPAD);
        const float2* Y2 = (const float2*)(d_ys + b*NPAD);
        const float2* Z2 = (const float2*)(d_zs + b*NPAD);
#pragma unroll
        for (int k = 0; k < PF2; ++k) {
            float2 xv = X2[k*GT + g], yv = Y2[k*GT + g], zv = Z2[k*GT + g];
            X[k] = f2pack(xv.x, xv.y);
            Y[k] = f2pack(yv.x, yv.y);
            Z[k] = f2pack(zv.x, zv.y);
        }
    }
    float dist[2*PF2];
#pragma unroll
    for (int i = 0; i < 2*PF2; ++i) dist[i] = 1e10f;

    __shared__ unsigned int s_val[NWARP]; __shared__ int s_idx[NWARP];
    __shared__ float s_wx[NWARP], s_wy[NWARP], s_wz[NWARP];
    __shared__ __align__(16) float s_mail[2][GPB][8];   // [parity][src rank]{v,idx,x,y,z}
    __shared__ __align__(8)  unsigned long long s_mbar;
    __shared__ float s_bc[3]; __shared__ int s_bci;

    const unsigned int mbar_a = smem_u32(&s_mbar);
    unsigned int remMail[GPB], remBar[GPB];
    {
        const unsigned int mail_my = smem_u32(&s_mail[0][rank][0]);
#pragma unroll
        for (int r = 0; r < GPB; ++r) {
            asm("mapa.shared::cluster.u32 %0, %1, %2;" : "=r"(remMail[r]) : "r"(mail_my), "r"(r));
            asm("mapa.shared::cluster.u32 %0, %1, %2;" : "=r"(remBar[r])  : "r"(mbar_a),  "r"(r));
        }
    }

    if (tid == 0) {
        asm volatile("mbarrier.init.shared.b64 [%0], %1;" :: "r"(mbar_a), "r"(GPB) : "memory");
    }
    __syncthreads();
    // one-time cluster sync: all mbarriers initialized before any remote arrive
    asm volatile("barrier.cluster.arrive.aligned;" ::: "memory");
    asm volatile("barrier.cluster.wait.aligned;"   ::: "memory");

    float cx = __ldg(d_xs + b*NPAD), cy = __ldg(d_ys + b*NPAD), cz = __ldg(d_zs + b*NPAD);
    int cur = 0;

    for (int t = 0; t < N_ALL; ++t) {
        if (rank == 0 && tid == 0) d_fps[b*N_ALL + t] = cur;

        unsigned long long ncx = f2pack(-cx, -cx);
        unsigned long long ncy = f2pack(-cy, -cy);
        unsigned long long ncz = f2pack(-cz, -cz);

        float best = -1.0f; int bidx = 0;
#pragma unroll
        for (int k = 0; k < PF2; ++k) {
            unsigned long long dx = f2add(X[k], ncx);
            unsigned long long dy = f2add(Y[k], ncy);
            unsigned long long dz = f2add(Z[k], ncz);
            // mul then summed adds (no fma) == reference elementwise lowering
            unsigned long long s = f2add(f2add(f2mul(dx,dx), f2mul(dy,dy)), f2mul(dz,dz));
            float lo, hi; f2unpack(s, lo, hi);
            float d0 = fminf(dist[2*k],   lo); dist[2*k]   = d0;
            float d1 = fminf(dist[2*k+1], hi); dist[2*k+1] = d1;
            int j0 = (k*GT + g)*2;
            if (d0 > best) { best = d0; bidx = j0;     }   // strict >: lowest index wins
            if (d1 > best) { best = d1; bidx = j0 + 1; }
        }

        // ---- warp argmax via redux (dist >= 0 after first pair, so u32 order == f32 order)
        {
            unsigned int vb = __float_as_uint(best);          // best >= 0 always
            unsigned int m  = redux_max_u32(vb);
            unsigned int cand = (vb == m) ? (unsigned int)bidx : 0x7fffffffu;
            unsigned int wi = redux_min_u32(cand);            // winning j, tie -> lowest j
            unsigned int bal = __ballot_sync(0xffffffffu, cand == wi);
            int src = __ffs(bal) - 1;                         // unique owner lane
            // owner extracts winner coords from its registers
            int wk = (int)(wi >> 12), h = (int)(wi & 1u);
            float wx = 0.f, wy = 0.f, wz = 0.f;
#pragma unroll
            for (int k2 = 0; k2 < PF2; ++k2) {
                if (k2 == wk) {
                    float a0, a1;
                    f2unpack(X[k2], a0, a1); wx = h ? a1 : a0;
                    f2unpack(Y[k2], a0, a1); wy = h ? a1 : a0;
                    f2unpack(Z[k2], a0, a1); wz = h ? a1 : a0;
                }
            }
            wx = __shfl_sync(0xffffffffu, wx, src);
            wy = __shfl_sync(0xffffffffu, wy, src);
            wz = __shfl_sync(0xffffffffu, wz, src);
            if (lane == 0) {
                s_val[wid] = m; s_idx[wid] = (int)wi;
                s_wx[wid] = wx; s_wy[wid] = wy; s_wz[wid] = wz;
            }
        }
        __syncthreads();

        if (wid == 0) {
            // ---- CTA reduce over 8 warp winners (redux) ----
            unsigned int vb = (lane < NWARP) ? s_val[lane] : 0u;
            unsigned int id = (lane < NWARP) ? (unsigned int)s_idx[lane] : 0x7fffffffu;
            float xx = (lane < NWARP) ? s_wx[lane] : 0.f;
            float yy = (lane < NWARP) ? s_wy[lane] : 0.f;
            float zz = (lane < NWARP) ? s_wz[lane] : 0.f;
            unsigned int m  = redux_max_u32(vb);
            unsigned int cand = (vb == m) ? id : 0x7fffffffu;
            unsigned int wi = redux_min_u32(cand);
            unsigned int bal = __ballot_sync(0xffffffffu, cand == wi);
            int src = __ffs(bal) - 1;
            xx = __shfl_sync(0xffffffffu, xx, src);
            yy = __shfl_sync(0xffffffffu, yy, src);
            zz = __shfl_sync(0xffffffffu, zz, src);

            // ---- publish candidate to all 8 CTAs' mailboxes (double-buffered) ----
            const unsigned int off_p = (unsigned)(t & 1) * (GPB*8*4);
            if (lane == 0) {
                float fv = __uint_as_float(m), fi = __int_as_float((int)wi);
#pragma unroll
                for (int r = 0; r < GPB; ++r) {
                    asm volatile("st.shared::cluster.v4.f32 [%0], {%1,%2,%3,%4};"
                                 :: "r"(remMail[r] + off_p), "f"(fv), "f"(fi),
                                    "f"(xx), "f"(yy) : "memory");
                    asm volatile("st.shared::cluster.f32 [%0], %1;"
                                 :: "r"(remMail[r] + off_p + 16), "f"(zz) : "memory");
                }
                asm volatile("fence.acq_rel.cluster;" ::: "memory");
#pragma unroll
                for (int r = 0; r < GPB; ++r)
                    asm volatile("mbarrier.arrive.shared::cluster.b64 _, [%0];"
                                 :: "r"(remBar[r]) : "memory");
            }
            // ---- wait local mbarrier: all 8 arrivals of this iteration ----
            {
                const unsigned int parity = (unsigned)(t & 1);
                unsigned int done;
                asm volatile(
                    "{\n\t.reg .pred p;\n\t"
                    "mbarrier.try_wait.parity.acquire.cta.shared::cta.b64 p, [%1], %2;\n\t"
                    "selp.b32 %0, 1, 0, p;\n\t}"
                    : "=r"(done) : "r"(mbar_a), "r"(parity) : "memory");
                if (!done) {
                    asm volatile(
                        "{\n\t.reg .pred P1;\n\t"
                        "WL_%=:\n\t"
                        "mbarrier.try_wait.parity.acquire.cta.shared::cta.b64 P1, [%0], %1, 0x989680;\n\t"
                        "@P1 bra.uni WD_%=;\n\t"
                        "bra.uni WL_%=;\n\t"
                        "WD_%=:\n\t}"
                        :: "r"(mbar_a), "r"(parity) : "memory");
                }
                asm volatile("fence.acq_rel.cluster;" ::: "memory");
            }
            // ---- pick across the 8 candidates (local smem, redux) ----
            {
                const float* mb = &s_mail[t & 1][0][0];
                unsigned int vb2 = (lane < GPB) ? __float_as_uint(mb[lane*8 + 0]) : 0u;
                unsigned int id2 = (lane < GPB) ? (unsigned int)__float_as_int(mb[lane*8 + 1]) : 0x7fffffffu;
                float xx2 = (lane < GPB) ? mb[lane*8 + 2] : 0.f;
                float yy2 = (lane < GPB) ? mb[lane*8 + 3] : 0.f;
                float zz2 = (lane < GPB) ? mb[lane*8 + 4] : 0.f;
                unsigned int m2  = redux_max_u32(vb2);
                unsigned int cand2 = (vb2 == m2) ? id2 : 0x7fffffffu;
                unsigned int wi2 = redux_min_u32(cand2);
                unsigned int bal2 = __ballot_sync(0xffffffffu, cand2 == wi2);
                int src2 = __ffs(bal2) - 1;
                xx2 = __shfl_sync(0xffffffffu, xx2, src2);
                yy2 = __shfl_sync(0xffffffffu, yy2, src2);
                zz2 = __shfl_sync(0xffffffffu, zz2, src2);
                if (lane == 0) { s_bc[0] = xx2; s_bc[1] = yy2; s_bc[2] = zz2; s_bci = (int)wi2; }
            }
        }
        __syncthreads();
        cx = s_bc[0]; cy = s_bc[1]; cz = s_bc[2]; cur = s_bci;
    }
}

// ---------------- 2: gather selected points (fps_idx[:, sel]) --------------------
__global__ void k_gather(const float* __restrict__ pc, const float* __restrict__ col,
                         const int* __restrict__ sel, float* __restrict__ out_coord) {
    int p = blockIdx.x*blockDim.x + threadIdx.x;
    if (p >= NROWS) return;
    int b = p >> 10, i = p & 1023;
    int gi = d_fps[b*N_ALL + sel[i]];
    const float* s  = pc  + ((long)b*N_IN + gi)*3;
    const float* s2 = col + ((long)b*N_IN + gi)*3;
    d_coord[p*3+0] = s[0];  d_coord[p*3+1] = s[1];  d_coord[p*3+2] = s[2];
    d_color[p*3+0] = s2[0]; d_color[p*3+1] = s2[1]; d_color[p*3+2] = s2[2];
    out_coord[p*3+0] = s[0]; out_coord[p*3+1] = s[1]; out_coord[p*3+2] = s[2];
}

// ---------------- 3: radius neighbors, one warp per query point ------------------
__global__ __launch_bounds__(256) void k_neighbor() {
    __shared__ float sx[NPT], sy[NPT], sz[NPT];
    const int b = blockIdx.y;
    for (int i = threadIdx.x; i < NPT; i += 256) {
        const float* cp = d_coord + (b*NPT + i)*3;
        sx[i] = cp[0]; sy[i] = cp[1]; sz[i] = cp[2];
    }
    __syncthreads();
    const int warp = threadIdx.x >> 5, lane = threadIdx.x & 31;
    const int pl = blockIdx.x*8 + warp;
    const int p  = b*NPT + pl;
    const float qx = sx[pl], qy = sy[pl], qz = sz[pl];
    const float R2 = 0.010000000000000002f;
    float key[32];
    int nv = 0;
#pragma unroll
    for (int i = 0; i < 32; ++i) {
        int c = i*32 + lane;
        float dx = __fadd_rn(qx, -sx[c]);
        float dy = __fadd_rn(qy, -sy[c]);
        float dz = __fadd_rn(qz, -sz[c]);
        float d2 = __fadd_rn(__fadd_rn(__fmul_rn(dx,dx), __fmul_rn(dy,dy)), __fmul_rn(dz,dz));
        bool v = (d2 <= R2);
        key[i] = v ? d2 : 1e10f;
        nv += v ? 1 : 0;
    }
    int total = nv;
#pragma unroll
    for (int off = 16; off > 0; off >>= 1) total += __shfl_xor_sync(0xffffffffu, total, off);

    int* my = d_nidx + p*KNB;
    if (total <= KNB) {
        int pos = 0;
#pragma unroll
        for (int i = 0; i < 32; ++i) {
            bool v = key[i] < 1e9f;
            unsigned m = __ballot_sync(0xffffffffu, v);
            if (v) my[pos + __popc(m & ((1u<<lane)-1u))] = i*32 + lane;
            pos += __popc(m);
        }
        for (int s = pos + lane; s < KNB; s += 32) my[s] = pl;  // padded slots: self
        if (lane == 0) d_ncnt[p] = total;
    } else {
        for (int s = 0; s < KNB; ++s) {
            float bv = 3e10f; int bi = 0x7fffffff;
#pragma unroll
            for (int i = 0; i < 32; ++i) {
                int c = i*32 + lane;
                if (key[i] < bv || (key[i] == bv && c < bi)) { bv = key[i]; bi = c; }
            }
#pragma unroll
            for (int off = 16; off > 0; off >>= 1) {
                float ov = __shfl_xor_sync(0xffffffffu, bv, off);
                int   oi = __shfl_xor_sync(0xffffffffu, bi, off);
                if (ov < bv || (ov == bv && oi < bi)) { bv = ov; bi = oi; }
            }
            if ((bi & 31) == lane) {
#pragma unroll
                for (int i = 0; i < 32; ++i) if (i*32 + lane == bi) key[i] = 2e10f;
            }
            if (lane == 0) my[s] = bi;
        }
        if (lane == 0) d_ncnt[p] = KNB;
    }
}

// ---------------- 4: x = feat@W_in+b ; q,k,v projections -------------------------
__global__ __launch_bounds__(96) void k_inproj(const float* __restrict__ Wi, const float* __restrict__ bi,
                                               const float* __restrict__ Wq, const float* __restrict__ Wk,
                                               const float* __restrict__ Wv) {
    __shared__ float sf[16][6];
    __shared__ float sx[16][96];
    const int t = threadIdx.x, r0 = blockIdx.x*16;
    {
        int r = t/6, j = t - r*6, row = r0 + r;
        sf[r][j] = (j < 3) ? d_color[row*3 + j] : d_coord[row*3 + j - 3];
    }
    __syncthreads();
    const int c = t;
    const float bc = bi[c];
#pragma unroll
    for (int r = 0; r < 16; ++r) {
        float a = bc;
#pragma unroll
        for (int j = 0; j < 6; ++j) a = __fmaf_rn(sf[r][j], Wi[j*96 + c], a);
        sx[r][c] = a;
        d_x[(r0 + r)*96 + c] = a;
    }
    __syncthreads();
    float aq[16], ak[16], av[16];
#pragma unroll
    for (int r = 0; r < 16; ++r) { aq[r] = 0.f; ak[r] = 0.f; av[r] = 0.f; }
    for (int j = 0; j < 96; ++j) {
        float wq = Wq[j*96 + c], wk = Wk[j*96 + c], wv = Wv[j*96 + c];
#pragma unroll
        for (int r = 0; r < 16; ++r) {
            float xv = sx[r][j];
            aq[r] = __fmaf_rn(xv, wq, aq[r]);
            ak[r] = __fmaf_rn(xv, wk, ak[r]);
            av[r] = __fmaf_rn(xv, wv, av[r]);
        }
    }
#pragma unroll
    for (int r = 0; r < 16; ++r) {
        d_qb[(r0 + r)*96 + c] = aq[r];
        d_kb[(r0 + r)*96 + c] = ak[r];
        d_vb[(r0 + r)*96 + c] = av[r];
    }
}

// ---------------- 5: local attention, one block per point ------------------------
__global__ __launch_bounds__(192) void k_attn(const float* __restrict__ Wpos) {
    const int p = blockIdx.x, pl = p & 1023, base = p - pl;
    const int t = threadIdx.x;
    __shared__ float sq[96];
    __shared__ float skn[KNB][96];
    __shared__ float svn[KNB][96];
    __shared__ float sdx[KNB], sdy[KNB], sdz[KNB];
    __shared__ int   snb[KNB];
    __shared__ float slog[HH*KNB];
    __shared__ int   scnt;

    if (t < KNB) {
        int nb = d_nidx[p*KNB + t];
        snb[t] = nb;
        int gn = base + nb;
        sdx[t] = __fadd_rn(d_coord[p*3+0], -d_coord[gn*3+0]);
        sdy[t] = __fadd_rn(d_coord[p*3+1], -d_coord[gn*3+1]);
        sdz[t] = __fadd_rn(d_coord[p*3+2], -d_coord[gn*3+2]);
    }
    if (t < 96) sq[t] = d_qb[p*96 + t];
    if (t == 0) scnt = d_ncnt[p];
    __syncthreads();

    for (int e = t; e < KNB*96; e += 192) {
        int kk = e / 96, c = e - kk*96;
        int gn = base + snb[kk];
        float pe = __fmaf_rn(sdz[kk], Wpos[192 + c],
                   __fmaf_rn(sdy[kk], Wpos[96 + c],
                   __fmul_rn(sdx[kk], Wpos[c])));
        skn[kk][c] = __fadd_rn(d_kb[gn*96 + c], pe);
        svn[kk][c] = __fadd_rn(d_vb[gn*96 + c], pe);
    }
    __syncthreads();

    const int cnt = scnt;
    for (int e = t; e < HH*KNB; e += 192) {
        int h = e / KNB, kk = e - h*KNB;
        float a = 0.f;
#pragma unroll
        for (int d = 0; d < 16; ++d) a = __fmaf_rn(sq[h*16 + d], skn[kk][h*16 + d], a);
        slog[h*KNB + kk] = (kk < cnt) ? __fmul_rn(a, 0.25f) : -1e9f;
    }
    __syncthreads();

    { // softmax: warp w == head w (6 warps exactly)
        int w = t >> 5, lane = t & 31;
        float v0 = slog[w*KNB + lane];
        float v1 = (lane < 2) ? slog[w*KNB + 32 + lane] : -3.0e38f;
        float m = fmaxf(v0, v1);
#pragma unroll
        for (int off = 16; off > 0; off >>= 1) m = fmaxf(m, __shfl_xor_sync(0xffffffffu, m, off));
        float e0 = expf(v0 - m);
        float e1 = (lane < 2) ? expf(v1 - m) : 0.f;
        float s = e0 + e1;
#pragma unroll
        for (int off = 16; off > 0; off >>= 1) s += __shfl_xor_sync(0xffffffffu, s, off);
        float inv = 1.0f / s;
        slog[w*KNB + lane] = e0 * inv;
        if (lane < 2) slog[w*KNB + 32 + lane] = e1 * inv;
    }
    __syncthreads();

    if (t < 96) {
        int h = t >> 4;
        float a = 0.f;
#pragma unroll
        for (int kk = 0; kk < KNB; ++kk) a = __fmaf_rn(slog[h*KNB + kk], svn[kk][t], a);
        d_ao[p*96 + t] = a;
    }
}

// ---------------- 6: x1 = LN(x + ao@Wo), one warp per row ------------------------
__global__ __launch_bounds__(256) void k_wo_ln(const float* __restrict__ Wo, const float* __restrict__ g1,
                                               const float* __restrict__ be1) {
    __shared__ float srow[8][96];
    const int w = threadIdx.x >> 5, lane = threadIdx.x & 31;
    const int r = blockIdx.x*8 + w;
    const int c0 = lane, c1 = lane + 32, c2 = lane + 64;
    srow[w][c0] = d_ao[r*96 + c0];
    srow[w][c1] = d_ao[r*96 + c1];
    srow[w][c2] = d_ao[r*96 + c2];
    float x0 = d_x[r*96 + c0], x1v = d_x[r*96 + c1], x2v = d_x[r*96 + c2];
    __syncwarp();
    float a0 = 0.f, a1 = 0.f, a2 = 0.f;
    for (int j = 0; j < 96; ++j) {
        float v = srow[w][j];
        a0 = __fmaf_rn(v, Wo[j*96 + c0], a0);
        a1 = __fmaf_rn(v, Wo[j*96 + c1], a1);
        a2 = __fmaf_rn(v, Wo[j*96 + c2], a2);
    }
    float y0 = __fadd_rn(x0, a0), y1 = __fadd_rn(x1v, a1), y2 = __fadd_rn(x2v, a2);
    float s = y0 + y1 + y2;
#pragma unroll
    for (int off = 16; off > 0; off >>= 1) s += __shfl_xor_sync(0xffffffffu, s, off);
    float m = s * (1.0f/96.0f);
    float d0 = y0 - m, d1 = y1 - m, d2 = y2 - m;
    float q = d0*d0 + d1*d1 + d2*d2;
#pragma unroll
    for (int off = 16; off > 0; off >>= 1) q += __shfl_xor_sync(0xffffffffu, q, off);
    float rs = rsqrtf(q*(1.0f/96.0f) + 1e-5f);
    d_x1[r*96 + c0] = __fmaf_rn(__fmul_rn(d0, rs), g1[c0], 0.f) + be1[c0];
    d_x1[r*96 + c1] = __fmaf_rn(__fmul_rn(d1, rs), g1[c1], 0.f) + be1[c1];
    d_x1[r*96 + c2] = __fmaf_rn(__fmul_rn(d2, rs), g1[c2], 0.f) + be1[c2];
}

// ---------------- 7: FFN + LN + transposed output --------------------------------
__global__ __launch_bounds__(384) void k_ffn(const float* __restrict__ W1, const float* __restrict__ b1,
                                             const float* __restrict__ W2, const float* __restrict__ b2,
                                             const float* __restrict__ g2, const float* __restrict__ be2,
                                             float* __restrict__ outF) {
    __shared__ float sx[16][96];
    __shared__ float sh[16][384];
    __shared__ float sy[16][96];
    __shared__ float sm[16], srs[16];
    const int t = threadIdx.x, r0 = blockIdx.x*16;

    for (int e = t; e < 16*96; e += 384) {
        int r = e / 96, c = e - r*96;
        sx[r][c] = d_x1[(r0 + r)*96 + c];
    }
    __syncthreads();
    { // hidden: col j = t
        int j = t;
        float acc[16];
        float bj = b1[j];
#pragma unroll
        for (int r = 0; r < 16; ++r) acc[r] = bj;
        for (int i = 0; i < 96; ++i) {
            float wv = W1[i*384 + j];
#pragma unroll
            for (int r = 0; r < 16; ++r) acc[r] = __fmaf_rn(sx[r][i], wv, acc[r]);
        }
#pragma unroll
        for (int r = 0; r < 16; ++r) sh[r][j] = fmaxf(acc[r], 0.f);
    }
    __syncthreads();
    { // output proj
        int g = t / 96, c = t - 96*g;
        float acc[4];
        float bc = b2[c];
#pragma unroll
        for (int rr = 0; rr < 4; ++rr) acc[rr] = bc;
        for (int j = 0; j < 384; ++j) {
            float wv = W2[j*96 + c];
#pragma unroll
            for (int rr = 0; rr < 4; ++rr) acc[rr] = __fmaf_rn(sh[g*4 + rr][j], wv, acc[rr]);
        }
#pragma unroll
        for (int rr = 0; rr < 4; ++rr) {
            int r = g*4 + rr;
            sy[r][c] = __fadd_rn(sx[r][c], acc[rr]);
        }
    }
    __syncthreads();
    if (t < 16) {
        float s = 0.f;
        for (int c = 0; c < 96; ++c) s += sy[t][c];
        float m = s * (1.0f/96.0f);
        float q = 0.f;
        for (int c = 0; c < 96; ++c) { float d = sy[t][c] - m; q += d*d; }
        sm[t] = m;
        srs[t] = rsqrtf(q*(1.0f/96.0f) + 1e-5f);
    }
    __syncthreads();
    {
        int g = t / 96, c = t - 96*g;
#pragma unroll
        for (int rr = 0; rr < 4; ++rr) {
            int r = g*4 + rr, row = r0 + r;
            float val = (sy[r][c] - sm[r]) * srs[r] * g2[c] + be2[c];
            int b = row >> 10, pl = row & 1023;
            outF[((long)b*96 + c)*1024 + pl] = val;
        }
    }
}

// ---------------- launch ----------------------------------------------------------
extern "C" void kernel_launch(void* const* d_in, const int* in_sizes, int n_in,
                              void* d_out, int out_size) {
    const float* pc   = (const float*)d_in[0];
    const float* col  = (const float*)d_in[1];
    const float* W_in = (const float*)d_in[2];
    const float* b_in = (const float*)d_in[3];
    const float* Wq   = (const float*)d_in[4];
    const float* Wk   = (const float*)d_in[5];
    const float* Wv   = (const float*)d_in[6];
    const float* Wo   = (const float*)d_in[7];
    const float* Wpos = (const float*)d_in[8];
    const float* W1   = (const float*)d_in[9];
    const float* b1   = (const float*)d_in[10];
    const float* W2   = (const float*)d_in[11];
    const float* b2   = (const float*)d_in[12];
    const float* g1   = (const float*)d_in[13];
    const float* be1  = (const float*)d_in[14];
    const float* g2   = (const float*)d_in[15];
    const float* be2  = (const float*)d_in[16];
    const int*   sel  = (const int*)d_in[17];
    float* out = (float*)d_out;

    k_transpose<<<(BB*NPAD + 255)/256, 256>>>(pc);
    k_fps<<<BB*GPB, FPS_T>>>();
    k_gather<<<(NROWS + 255)/256, 256>>>(pc, col, sel, out + (long)BB*CC*NPT);
    k_neighbor<<<dim3(NPT/8, BB), 256>>>();
    k_inproj<<<NROWS/16, 96>>>(W_in, b_in, Wq, Wk, Wv);
    k_attn<<<NROWS, 192>>>(Wpos);
    k_wo_ln<<<NROWS/8, 256>>>(Wo, g1, be1);
    k_ffn<<<NROWS/16, 384>>>(W1, b1, W2, b2, g2, be2, out);
}